// round 9
// baseline (speedup 1.0000x reference)
#include <cuda_runtime.h>
#include <cuda_bf16.h>
#include <math.h>
#include <stdint.h>

#define B_    2
#define T_    2048
#define D_    2048
#define H_    16
#define KVH_  4
#define HD_   128
#define NTOK  (B_*T_)

// ---------------- scratch (device globals: allocation-free) ----------------
__device__ float g_q  [NTOK*D_];
__device__ float g_k  [NTOK*KVH_*HD_];
__device__ float g_v  [NTOK*KVH_*HD_];
__device__ float g_g  [NTOK*D_];
__device__ float g_o  [NTOK*D_];
// split-bf16 operands
__device__ __align__(16) __nv_bfloat16 g_ah [NTOK*D_];
__device__ __align__(16) __nv_bfloat16 g_al [NTOK*D_];
__device__ __align__(16) __nv_bfloat16 g_akh[NTOK*D_];
__device__ __align__(16) __nv_bfloat16 g_akl[NTOK*D_];
__device__ __align__(16) __nv_bfloat16 g_avh[NTOK*D_];
__device__ __align__(16) __nv_bfloat16 g_avl[NTOK*D_];
__device__ __align__(16) __nv_bfloat16 g_wth[2*D_*D_];
__device__ __align__(16) __nv_bfloat16 g_wtl[2*D_*D_];
// pre-split attention operands
__device__ __align__(16) __nv_bfloat16 g_qh [NTOK*D_];
__device__ __align__(16) __nv_bfloat16 g_ql [NTOK*D_];
__device__ __align__(16) __nv_bfloat16 g_kh [NTOK*KVH_*HD_];
__device__ __align__(16) __nv_bfloat16 g_kl [NTOK*KVH_*HD_];
__device__ __align__(16) __nv_bfloat16 g_vh [NTOK*KVH_*HD_];
__device__ __align__(16) __nv_bfloat16 g_vl [NTOK*KVH_*HD_];

// ================= baseline-ISA helpers =================
__device__ __forceinline__ uint32_t smem_u32(const void* p) {
    uint32_t a;
    asm("{ .reg .u64 t; cvta.to.shared.u64 t, %1; cvt.u32.u64 %0, t; }" : "=r"(a) : "l"(p));
    return a;
}
__device__ __forceinline__ uint32_t sw128(uint32_t off) { return off ^ ((off >> 3) & 0x70); }
__device__ __forceinline__ uint32_t sw256(uint32_t off) { return off ^ ((off >> 4) & 0x70); }

__device__ __forceinline__ void cp_async16(uint32_t dst, const void* src) {
    asm volatile("cp.async.cg.shared.global [%0], [%1], 16;" :: "r"(dst), "l"(src) : "memory");
}
#define CP_COMMIT() asm volatile("cp.async.commit_group;" ::: "memory")
#define CP_WAIT(n)  asm volatile("cp.async.wait_group %0;" :: "n"(n) : "memory")

__device__ __forceinline__ void ldsm_x4(uint32_t* r, uint32_t addr) {
    asm volatile("ldmatrix.sync.aligned.m8n8.x4.shared.b16 {%0,%1,%2,%3}, [%4];"
                 : "=r"(r[0]), "=r"(r[1]), "=r"(r[2]), "=r"(r[3]) : "r"(addr));
}
__device__ __forceinline__ void ldsm_x4_t(uint32_t* r, uint32_t addr) {
    asm volatile("ldmatrix.sync.aligned.m8n8.x4.trans.shared.b16 {%0,%1,%2,%3}, [%4];"
                 : "=r"(r[0]), "=r"(r[1]), "=r"(r[2]), "=r"(r[3]) : "r"(addr));
}
__device__ __forceinline__ void mma16816(float* d, const uint32_t* a, const uint32_t* b) {
    asm volatile("mma.sync.aligned.m16n8k16.row.col.f32.bf16.bf16.f32 "
                 "{%0,%1,%2,%3}, {%4,%5,%6,%7}, {%8,%9}, {%0,%1,%2,%3};"
                 : "+f"(d[0]), "+f"(d[1]), "+f"(d[2]), "+f"(d[3])
                 : "r"(a[0]), "r"(a[1]), "r"(a[2]), "r"(a[3]), "r"(b[0]), "r"(b[1]));
}

// fast exp on the FMA pipe
__device__ __forceinline__ float fast_exp(float x) {
    x = fmaxf(x, -80.f);
    const float LOG2E = 1.4426950408889634f;
    float t = x * LOG2E;
    float r = t + 12582912.f;
    float i = r - 12582912.f;
    float f = t - i;
    uint32_t ib = __float_as_uint(r);
    float sc = __uint_as_float((ib + 127u) << 23);
    float p = 1.3333558146e-3f;
    p = fmaf(p, f, 9.6181291076e-3f);
    p = fmaf(p, f, 5.5504108664e-2f);
    p = fmaf(p, f, 2.4022650696e-1f);
    p = fmaf(p, f, 6.9314718056e-1f);
    p = fmaf(p, f, 1.0f);
    return p * sc;
}

__device__ __forceinline__ void split2(float a, float b, uint32_t& hp, uint32_t& lp) {
    __nv_bfloat16 ha = __float2bfloat16(a), hb = __float2bfloat16(b);
    __nv_bfloat16 la = __float2bfloat16(a - __bfloat162float(ha));
    __nv_bfloat16 lb = __float2bfloat16(b - __bfloat162float(hb));
    hp = ((uint32_t)__bfloat16_as_ushort(hb) << 16) | __bfloat16_as_ushort(ha);
    lp = ((uint32_t)__bfloat16_as_ushort(lb) << 16) | __bfloat16_as_ushort(la);
}

// ================= elementwise kernels =================
__global__ void split_x_kernel(const float* __restrict__ x,
                               __nv_bfloat16* __restrict__ hi,
                               __nv_bfloat16* __restrict__ lo)
{
    int i = blockIdx.x * blockDim.x + threadIdx.x;
    float4 v = ((const float4*)x)[i];
    uint32_t h0, l0, h1, l1;
    split2(v.x, v.y, h0, l0);
    split2(v.z, v.w, h1, l1);
    ((uint2*)hi)[i] = make_uint2(h0, h1);
    ((uint2*)lo)[i] = make_uint2(l0, l1);
}

// fused time-shift mix + bf16 hi/lo split for k and v paths
__global__ void mix_split_kernel(const float* __restrict__ xk, const float* __restrict__ xv,
                                 const float* __restrict__ mk, const float* __restrict__ mv,
                                 __nv_bfloat16* __restrict__ kh, __nv_bfloat16* __restrict__ kl,
                                 __nv_bfloat16* __restrict__ vh, __nv_bfloat16* __restrict__ vl)
{
    const int D4 = D_ / 4;
    int idx = blockIdx.x * blockDim.x + threadIdx.x;
    int d4  = idx & (D4 - 1);
    int tok = idx >> 9;
    int t   = tok & (T_ - 1);

    float4 kc = ((const float4*)xk)[idx];
    float4 vc = ((const float4*)xv)[idx];
    float4 m1 = ((const float4*)mk)[d4];
    float4 m2 = ((const float4*)mv)[d4];
    float4 kp = make_float4(0.f,0.f,0.f,0.f);
    float4 vp = make_float4(0.f,0.f,0.f,0.f);
    if (t > 0) {
        kp = ((const float4*)xk)[idx - D4];
        vp = ((const float4*)xv)[idx - D4];
    }
    float4 r1, r2;
    r1.x = kc.x + m1.x*(kp.x-kc.x);  r1.y = kc.y + m1.y*(kp.y-kc.y);
    r1.z = kc.z + m1.z*(kp.z-kc.z);  r1.w = kc.w + m1.w*(kp.w-kc.w);
    r2.x = vc.x + m2.x*(vp.x-vc.x);  r2.y = vc.y + m2.y*(vp.y-vc.y);
    r2.z = vc.z + m2.z*(vp.z-vc.z);  r2.w = vc.w + m2.w*(vp.w-vc.w);

    uint32_t h0, l0, h1, l1;
    split2(r1.x, r1.y, h0, l0);  split2(r1.z, r1.w, h1, l1);
    ((uint2*)kh)[idx] = make_uint2(h0, h1);
    ((uint2*)kl)[idx] = make_uint2(l0, l1);
    split2(r2.x, r2.y, h0, l0);  split2(r2.z, r2.w, h1, l1);
    ((uint2*)vh)[idx] = make_uint2(h0, h1);
    ((uint2*)vl)[idx] = make_uint2(l0, l1);
}

// W[K=2048, N] -> Wt_hi/lo [N, 2048] transposed split; vectorized 8B stores.
// Tile: 128 k-rows x 32 n-cols. Block (32, 32) = 1024 threads.
__global__ void wsplit_t_kernel(const float* __restrict__ W,
                                __nv_bfloat16* __restrict__ th,
                                __nv_bfloat16* __restrict__ tl, int N)
{
    __shared__ float s[32][132];   // [n][k] after transpose-on-store
    const int k0 = blockIdx.y * 128, n0 = blockIdx.x * 32;
    const int tx = threadIdx.x, ty = threadIdx.y;
    const int tid = ty * 32 + tx;

#pragma unroll
    for (int i = 0; i < 4; i++) {
        int kk = ty + 32*i;
        s[tx][kk] = W[(size_t)(k0 + kk) * N + n0 + tx];
    }
    __syncthreads();

    const int r = tid >> 5, seg = tid & 31;   // row n0+r, k = k0 + seg*4
    float4 v = *(const float4*)(&s[r][seg << 2]);
    uint32_t h0, l0, h1, l1;
    split2(v.x, v.y, h0, l0);
    split2(v.z, v.w, h1, l1);
    size_t o = ((size_t)(n0 + r) * D_ + k0 + (seg << 2)) >> 2;  // uint2 index
    ((uint2*)th)[o] = make_uint2(h0, h1);
    ((uint2*)tl)[o] = make_uint2(l0, l1);
}

// ================= split-bf16 GEMM via mma.sync (16 warps) =================
// Block tile 128x128, BK=64, 512 threads; warp grid 4(M) x 4(N), warp tile 32x32.
#define GK        2048
#define NCH       (GK/64)
#define TILEB     16384
#define STAGEB    (4*TILEB)
#define GEMM_SMEM (3*STAGEB + 1024)

__global__ void __launch_bounds__(512, 1) gemm_mma_kernel(
    const __nv_bfloat16* __restrict__ ah, const __nv_bfloat16* __restrict__ al,
    const __nv_bfloat16* __restrict__ wth, const __nv_bfloat16* __restrict__ wtl,
    float* __restrict__ C0, float* __restrict__ C1, int cstride)
{
    extern __shared__ char sm[];
    const uint32_t smb   = smem_u32(sm);
    const uint32_t tiles = (smb + 1023u) & ~1023u;

    const int tid  = threadIdx.x;
    const int wid  = tid >> 5, lane = tid & 31;
    const int wm   = wid & 3,  wn   = wid >> 2;     // 4 x 4 warps
    const int m0   = blockIdx.y << 7;
    const int n0   = blockIdx.x << 7;

    const __nv_bfloat16* srcs[4] = { ah  + (size_t)m0 * GK, al  + (size_t)m0 * GK,
                                     wth + (size_t)n0 * GK, wtl + (size_t)n0 * GK };

    float acc[2][4][4];
#pragma unroll
    for (int i = 0; i < 2; i++)
#pragma unroll
        for (int j = 0; j < 4; j++)
#pragma unroll
            for (int q = 0; q < 4; q++) acc[i][j][q] = 0.f;

    auto prefetch = [&](int ch) {
        const uint32_t stage = tiles + (uint32_t)(ch % 3) * STAGEB;
        const int ke = ch << 6;
#pragma unroll
        for (int j = 0; j < 8; j++) {
            int f   = tid + (j << 9);       // 0..4095
            int t   = f >> 10;
            int idx = f & 1023;
            int r   = idx >> 3;
            int c   = idx & 7;
            cp_async16(stage + t * TILEB + sw128((r << 7) + (c << 4)),
                       srcs[t] + (size_t)r * GK + ke + (c << 3));
        }
        CP_COMMIT();
    };

    prefetch(0);
    prefetch(1);

    for (int ch = 0; ch < NCH; ch++) {
        if (ch + 2 < NCH)      { prefetch(ch + 2); CP_WAIT(2); }
        else if (ch + 1 < NCH) { CP_WAIT(1); }
        else                   { CP_WAIT(0); }
        __syncthreads();

        const uint32_t stage = tiles + (uint32_t)(ch % 3) * STAGEB;
        const uint32_t sAh = stage,            sAl = stage + TILEB;
        const uint32_t sBh = stage + 2*TILEB,  sBl = stage + 3*TILEB;

#pragma unroll
        for (int ks = 0; ks < 4; ks++) {
            const int kb = ks << 5;

            uint32_t ahf[2][4], alf[2][4], bhf[2][4], blf[2][4];
#pragma unroll
            for (int mt = 0; mt < 2; mt++) {
                int row = wm*32 + mt*16 + (lane & 15);
                uint32_t off = sw128((uint32_t)(row << 7) + kb + ((lane >> 4) << 4));
                ldsm_x4(ahf[mt], sAh + off);
                ldsm_x4(alf[mt], sAl + off);
            }
            const int brow = wn*32 + (lane & 7) + ((lane >> 4) << 3);
            const int bko  = kb + (((lane >> 3) & 1) << 4);
#pragma unroll
            for (int np = 0; np < 2; np++) {
                uint32_t off = sw128((uint32_t)((brow + np*16) << 7) + bko);
                ldsm_x4(bhf[np], sBh + off);
                ldsm_x4(blf[np], sBl + off);
            }
            // pass 1: hi*hi
#pragma unroll
            for (int mt = 0; mt < 2; mt++)
#pragma unroll
                for (int np = 0; np < 2; np++) {
                    mma16816(acc[mt][2*np],   ahf[mt], bhf[np]);
                    mma16816(acc[mt][2*np+1], ahf[mt], bhf[np] + 2);
                }
            // pass 2: hi*lo
#pragma unroll
            for (int mt = 0; mt < 2; mt++)
#pragma unroll
                for (int np = 0; np < 2; np++) {
                    mma16816(acc[mt][2*np],   ahf[mt], blf[np]);
                    mma16816(acc[mt][2*np+1], ahf[mt], blf[np] + 2);
                }
            // pass 3: lo*hi
#pragma unroll
            for (int mt = 0; mt < 2; mt++)
#pragma unroll
                for (int np = 0; np < 2; np++) {
                    mma16816(acc[mt][2*np],   alf[mt], bhf[np]);
                    mma16816(acc[mt][2*np+1], alf[mt], bhf[np] + 2);
                }
        }
        __syncthreads();
    }

    float* C = C0;
    int nc = n0;
    if (C1 != nullptr && n0 >= cstride) { C = C1; nc = n0 - cstride; }

    const int er = lane >> 2, ec = (lane & 3) << 1;
#pragma unroll
    for (int mt = 0; mt < 2; mt++) {
        int r0 = m0 + wm*32 + mt*16 + er;
#pragma unroll
        for (int nt = 0; nt < 4; nt++) {
            int c = nc + wn*32 + nt*8 + ec;
            *(float2*)(C + (size_t)r0      * cstride + c) = make_float2(acc[mt][nt][0], acc[mt][nt][1]);
            *(float2*)(C + (size_t)(r0 + 8)* cstride + c) = make_float2(acc[mt][nt][2], acc[mt][nt][3]);
        }
    }
}

// ------- per-head RMS norm (+ optional RoPE), emits bf16 hi/lo split -------
__global__ void norm_head_split_kernel(const float* __restrict__ x, int heads,
                                       int do_rope, float scale,
                                       __nv_bfloat16* __restrict__ oh,
                                       __nv_bfloat16* __restrict__ ol)
{
    __shared__ float sbuf[4];
    __shared__ float svals[128];
    const int head = blockIdx.x % heads;
    const int tok  = blockIdx.x / heads;
    const int t    = tok % T_;
    const size_t base = (size_t)tok*heads*HD_ + head*HD_;
    const float* p = x + base;
    const int d = threadIdx.x;

    float v  = p[d];
    float ss = v*v;
#pragma unroll
    for (int o = 16; o > 0; o >>= 1) ss += __shfl_xor_sync(0xffffffffu, ss, o);
    if ((d & 31) == 0) sbuf[d >> 5] = ss;
    __syncthreads();
    float tot = sbuf[0] + sbuf[1] + sbuf[2] + sbuf[3];
    float r   = rsqrtf(tot * (1.f/HD_) + 1e-8f);
    float vn  = v * r;
    float f;

    if (do_rope) {
        svals[d] = vn;
        __syncthreads();
        int   j  = d & 63;
        float inv_freq = exp2f(-(float)j * (13.287712379549449f / 64.f));
        float ang = (float)t * inv_freq;
        float sn, cs;
        sincosf(ang, &sn, &cs);
        float partner = svals[d ^ 64];
        f = (d < 64) ? (vn*cs - partner*sn) : (vn*cs + partner*sn);
    } else {
        f = vn;
    }
    f *= scale;
    __nv_bfloat16 h = __float2bfloat16(f);
    __nv_bfloat16 l = __float2bfloat16(f - __bfloat162float(h));
    oh[base + d] = h;
    ol[base + d] = l;
}

// ================= flash attention via mma.sync (fused gate epilogue) ======
#define FQH  0
#define FQL  32768
#define FKV  65536
#define FSTG 65536
#define FLASH_SMEM (FKV + 2*FSTG)

__global__ void __launch_bounds__(256, 1) flash_mma_kernel(
    const __nv_bfloat16* __restrict__ qh, const __nv_bfloat16* __restrict__ ql,
    const __nv_bfloat16* __restrict__ kh, const __nv_bfloat16* __restrict__ kl,
    const __nv_bfloat16* __restrict__ vh, const __nv_bfloat16* __restrict__ vl,
    const float* __restrict__ g,
    __nv_bfloat16* __restrict__ oh_out, __nv_bfloat16* __restrict__ ol_out)
{
    extern __shared__ char sm[];
    const uint32_t smb = smem_u32(sm);

    const int tid  = threadIdx.x;
    const int w    = tid >> 5, lane = tid & 31;
    const int qt   = blockIdx.x;
    const int b    = blockIdx.y >> 4;
    const int h    = blockIdx.y & 15;
    const int kvh  = h >> 2;
    const int qs   = qt << 7;

    // ---- async load Q tile (128x128 bf16 hi+lo) ----
    {
        const __nv_bfloat16* qgh = qh + ((size_t)(b*T_ + qs))*D_ + h*HD_;
        const __nv_bfloat16* qgl = ql + ((size_t)(b*T_ + qs))*D_ + h*HD_;
#pragma unroll
        for (int it = 0; it < 8; it++) {
            int idx = tid + (it << 8);
            int r = idx >> 4, c = idx & 15;
            uint32_t off = sw256((r << 8) + (c << 4));
            cp_async16(smb + FQH + off, qgh + (size_t)r*D_ + (c << 3));
            cp_async16(smb + FQL + off, qgl + (size_t)r*D_ + (c << 3));
        }
        CP_COMMIT();
    }

    const __nv_bfloat16* kh_b = kh + (size_t)(b*T_)*(KVH_*HD_) + kvh*HD_;
    const __nv_bfloat16* kl_b = kl + (size_t)(b*T_)*(KVH_*HD_) + kvh*HD_;
    const __nv_bfloat16* vh_b = vh + (size_t)(b*T_)*(KVH_*HD_) + kvh*HD_;
    const __nv_bfloat16* vl_b = vl + (size_t)(b*T_)*(KVH_*HD_) + kvh*HD_;

    auto prefetch_kv = [&](int kt) {
        const uint32_t sb = smb + FKV + (uint32_t)(kt & 1)*FSTG;
        const size_t rb = (size_t)(kt << 6) * (KVH_*HD_);
        const __nv_bfloat16* ps[4] = { kh_b + rb, kl_b + rb, vh_b + rb, vl_b + rb };
#pragma unroll
        for (int t = 0; t < 4; t++) {
#pragma unroll
            for (int it = 0; it < 4; it++) {
                int idx = tid + (it << 8);
                int r = idx >> 4, c = idx & 15;
                cp_async16(sb + t*16384 + sw256((r << 8) + (c << 4)),
                           ps[t] + (size_t)r*(KVH_*HD_) + (c << 3));
            }
        }
        CP_COMMIT();
    };

    prefetch_kv(0);

    float o[16][4];
#pragma unroll
    for (int nh = 0; nh < 16; nh++)
#pragma unroll
        for (int qq = 0; qq < 4; qq++) o[nh][qq] = 0.f;
    float m0 = -1e30f, m1 = -1e30f, l0 = 0.f, l1 = 0.f;

    const int nkv = 2*qt + 2;
    for (int kt = 0; kt < nkv; kt++) {
        const int ks = kt << 6;
        if (kt + 1 < nkv) { prefetch_kv(kt + 1); CP_WAIT(1); }
        else              { CP_WAIT(0); }
        __syncthreads();

        const uint32_t sb  = smb + FKV + (uint32_t)(kt & 1)*FSTG;
        const uint32_t sKH = sb, sKL = sb + 16384, sVH = sb + 32768, sVL = sb + 49152;

        // ---- S = Q K^T (term-major) ----
        float s[8][4];
#pragma unroll
        for (int nt = 0; nt < 8; nt++)
#pragma unroll
            for (int qq = 0; qq < 4; qq++) s[nt][qq] = 0.f;

#pragma unroll
        for (int ks8 = 0; ks8 < 8; ks8++) {
            const int kb = ks8 << 5;
            uint32_t aQh[4], aQl[4], bhf[4][4], blf[4][4];
            {
                int row = (w << 4) + (lane & 15);
                uint32_t off = sw256((uint32_t)(row << 8) + kb + ((lane >> 4) << 4));
                ldsm_x4(aQh, smb + FQH + off);
                ldsm_x4(aQl, smb + FQL + off);
            }
            const int brow4 = (lane & 7) + ((lane >> 4) << 3);
            const int bko   = kb + (((lane >> 3) & 1) << 4);
#pragma unroll
            for (int np = 0; np < 4; np++) {
                uint32_t off = sw256((uint32_t)((brow4 + np*16) << 8) + bko);
                ldsm_x4(bhf[np], sKH + off);
                ldsm_x4(blf[np], sKL + off);
            }
#pragma unroll
            for (int np = 0; np < 4; np++) {
                mma16816(s[2*np],   aQh, bhf[np]);
                mma16816(s[2*np+1], aQh, bhf[np] + 2);
            }
#pragma unroll
            for (int np = 0; np < 4; np++) {
                mma16816(s[2*np],   aQh, blf[np]);
                mma16816(s[2*np+1], aQh, blf[np] + 2);
            }
#pragma unroll
            for (int np = 0; np < 4; np++) {
                mma16816(s[2*np],   aQl, bhf[np]);
                mma16816(s[2*np+1], aQl, bhf[np] + 2);
            }
        }

        // ---- causal mask ----
        if (kt >= 2*qt) {
            const int gr0 = qs + (w << 4) + (lane >> 2);
            const int gc0 = ks + ((lane & 3) << 1);
#pragma unroll
            for (int nt = 0; nt < 8; nt++) {
                int c = gc0 + nt*8;
                if (c     > gr0)     s[nt][0] = -1e30f;
                if (c + 1 > gr0)     s[nt][1] = -1e30f;
                if (c     > gr0 + 8) s[nt][2] = -1e30f;
                if (c + 1 > gr0 + 8) s[nt][3] = -1e30f;
            }
        }

        // ---- online softmax ----
        float mx0 = -1e30f, mx1 = -1e30f;
#pragma unroll
        for (int nt = 0; nt < 8; nt++) {
            mx0 = fmaxf(mx0, fmaxf(s[nt][0], s[nt][1]));
            mx1 = fmaxf(mx1, fmaxf(s[nt][2], s[nt][3]));
        }
        mx0 = fmaxf(mx0, __shfl_xor_sync(0xffffffffu, mx0, 1));
        mx0 = fmaxf(mx0, __shfl_xor_sync(0xffffffffu, mx0, 2));
        mx1 = fmaxf(mx1, __shfl_xor_sync(0xffffffffu, mx1, 1));
        mx1 = fmaxf(mx1, __shfl_xor_sync(0xffffffffu, mx1, 2));
        float m0n = fmaxf(m0, mx0), m1n = fmaxf(m1, mx1);
        float sc0 = fast_exp(m0 - m0n), sc1 = fast_exp(m1 - m1n);
        m0 = m0n; m1 = m1n;

        float sum0 = 0.f, sum1 = 0.f;
#pragma unroll
        for (int nt = 0; nt < 8; nt++) {
            s[nt][0] = fast_exp(s[nt][0] - m0n); sum0 += s[nt][0];
            s[nt][1] = fast_exp(s[nt][1] - m0n); sum0 += s[nt][1];
            s[nt][2] = fast_exp(s[nt][2] - m1n); sum1 += s[nt][2];
            s[nt][3] = fast_exp(s[nt][3] - m1n); sum1 += s[nt][3];
        }
        sum0 += __shfl_xor_sync(0xffffffffu, sum0, 1);
        sum0 += __shfl_xor_sync(0xffffffffu, sum0, 2);
        sum1 += __shfl_xor_sync(0xffffffffu, sum1, 1);
        sum1 += __shfl_xor_sync(0xffffffffu, sum1, 2);
        l0 = l0*sc0 + sum0;
        l1 = l1*sc1 + sum1;

#pragma unroll
        for (int nh = 0; nh < 16; nh++) {
            o[nh][0] *= sc0; o[nh][1] *= sc0;
            o[nh][2] *= sc1; o[nh][3] *= sc1;
        }

        // ---- O += P V (term-major over nhp pairs) ----
#pragma unroll
        for (int j = 0; j < 4; j++) {
            uint32_t aPh[4], aPl[4];
            split2(s[2*j][0],   s[2*j][1],   aPh[0], aPl[0]);
            split2(s[2*j][2],   s[2*j][3],   aPh[1], aPl[1]);
            split2(s[2*j+1][0], s[2*j+1][1], aPh[2], aPl[2]);
            split2(s[2*j+1][2], s[2*j+1][3], aPh[3], aPl[3]);
            const uint32_t vrow = (j << 4) + (lane & 15);
            const uint32_t nsel = (lane >> 4);
#pragma unroll
            for (int pp = 0; pp < 4; pp++) {
                uint32_t bh0[4], bl0[4], bh1[4], bl1[4];
                uint32_t off0 = sw256((vrow << 8) + ((4*pp     + nsel) << 4));
                uint32_t off1 = sw256((vrow << 8) + ((4*pp + 2 + nsel) << 4));
                ldsm_x4_t(bh0, sVH + off0);
                ldsm_x4_t(bl0, sVL + off0);
                ldsm_x4_t(bh1, sVH + off1);
                ldsm_x4_t(bl1, sVL + off1);
                mma16816(o[4*pp],   aPh, bh0);
                mma16816(o[4*pp+1], aPh, bh0 + 2);
                mma16816(o[4*pp+2], aPh, bh1);
                mma16816(o[4*pp+3], aPh, bh1 + 2);
                mma16816(o[4*pp],   aPl, bh0);
                mma16816(o[4*pp+1], aPl, bh0 + 2);
                mma16816(o[4*pp+2], aPl, bh1);
                mma16816(o[4*pp+3], aPl, bh1 + 2);
                mma16816(o[4*pp],   aPh, bl0);
                mma16816(o[4*pp+1], aPh, bl0 + 2);
                mma16816(o[4*pp+2], aPh, bl1);
                mma16816(o[4*pp+3], aPh, bl1 + 2);
            }
        }
        __syncthreads();
    }

    // ---- fused epilogue: 1/l, per-head L2 norm, gate, split-bf16 out ----
    const float inv0 = 1.f / l0, inv1 = 1.f / l1;
    float y0[16][2], y1[16][2];
    float ss0 = 0.f, ss1 = 0.f;
#pragma unroll
    for (int nh = 0; nh < 16; nh++) {
        y0[nh][0] = o[nh][0]*inv0;  y0[nh][1] = o[nh][1]*inv0;
        y1[nh][0] = o[nh][2]*inv1;  y1[nh][1] = o[nh][3]*inv1;
        ss0 += y0[nh][0]*y0[nh][0] + y0[nh][1]*y0[nh][1];
        ss1 += y1[nh][0]*y1[nh][0] + y1[nh][1]*y1[nh][1];
    }
    ss0 += __shfl_xor_sync(0xffffffffu, ss0, 1);
    ss0 += __shfl_xor_sync(0xffffffffu, ss0, 2);
    ss1 += __shfl_xor_sync(0xffffffffu, ss1, 1);
    ss1 += __shfl_xor_sync(0xffffffffu, ss1, 2);
    const float s0 = 1.f / fmaxf(sqrtf(ss0), 1e-12f);
    const float s1 = 1.f / fmaxf(sqrtf(ss1), 1e-12f);

    const int r0 = qs + (w << 4) + (lane >> 2);
    const size_t base0 = ((size_t)(b*T_) + r0)*D_ + h*HD_ + ((lane & 3) << 1);
    const size_t base1 = base0 + (size_t)8*D_;
#pragma unroll
    for (int nh = 0; nh < 16; nh++) {
        float2 gv0 = *(const float2*)(g + base0 + nh*8);
        float2 gv1 = *(const float2*)(g + base1 + nh*8);
        uint32_t hp, lp;
        split2(gv0.x*y0[nh][0]*s0, gv0.y*y0[nh][1]*s0, hp, lp);
        *(uint32_t*)(oh_out + base0 + nh*8) = hp;
        *(uint32_t*)(ol_out + base0 + nh*8) = lp;
        split2(gv1.x*y1[nh][0]*s1, gv1.y*y1[nh][1]*s1, hp, lp);
        *(uint32_t*)(oh_out + base1 + nh*8) = hp;
        *(uint32_t*)(ol_out + base1 + nh*8) = lp;
    }
}

// ---------------- final RMS norm over D, scaled by 1/sqrt(48) ----------------
__global__ void final_norm_kernel(const float* __restrict__ in, float* __restrict__ out)
{
    __shared__ float sbuf[8];
    const int tok = blockIdx.x;
    const float* p = in + (size_t)tok*D_;
    const int base = threadIdx.x * 8;

    float4 a = *(const float4*)(p + base);
    float4 b = *(const float4*)(p + base + 4);
    float ss = a.x*a.x + a.y*a.y + a.z*a.z + a.w*a.w
             + b.x*b.x + b.y*b.y + b.z*b.z + b.w*b.w;
#pragma unroll
    for (int o = 16; o > 0; o >>= 1) ss += __shfl_xor_sync(0xffffffffu, ss, o);
    if ((threadIdx.x & 31) == 0) sbuf[threadIdx.x >> 5] = ss;
    __syncthreads();
    float tot = 0.f;
#pragma unroll
    for (int i = 0; i < 8; i++) tot += sbuf[i];
    float r = rsqrtf(tot * (1.f/D_) + 1e-8f) * 0.14433756729740643f;

    float* q = out + (size_t)tok*D_;
    a.x*=r; a.y*=r; a.z*=r; a.w*=r;
    b.x*=r; b.y*=r; b.z*=r; b.w*=r;
    *(float4*)(q + base)     = a;
    *(float4*)(q + base + 4) = b;
}

// ---------------- launcher ----------------
extern "C" void kernel_launch(void* const* d_in, const int* in_sizes, int n_in,
                              void* d_out, int out_size)
{
    (void)in_sizes; (void)n_in; (void)out_size;
    const float* xq = (const float*)d_in[0];
    const float* xk = (const float*)d_in[1];
    const float* xv = (const float*)d_in[2];
    const float* Wq = (const float*)d_in[3];
    const float* Wk = (const float*)d_in[4];
    const float* Wv = (const float*)d_in[5];
    const float* Wg = (const float*)d_in[6];
    const float* Wo = (const float*)d_in[7];
    const float* mk = (const float*)d_in[8];
    const float* mv = (const float*)d_in[9];
    float* out = (float*)d_out;

    float *pq, *pk, *pv, *pg, *po;
    __nv_bfloat16 *pah, *pal, *pakh, *pakl, *pavh, *pavl, *pwth, *pwtl;
    __nv_bfloat16 *pqh, *pql, *pkh, *pkl, *pvh, *pvl;
    cudaGetSymbolAddress((void**)&pq,   g_q);
    cudaGetSymbolAddress((void**)&pk,   g_k);
    cudaGetSymbolAddress((void**)&pv,   g_v);
    cudaGetSymbolAddress((void**)&pg,   g_g);
    cudaGetSymbolAddress((void**)&po,   g_o);
    cudaGetSymbolAddress((void**)&pah,  g_ah);
    cudaGetSymbolAddress((void**)&pal,  g_al);
    cudaGetSymbolAddress((void**)&pakh, g_akh);
    cudaGetSymbolAddress((void**)&pakl, g_akl);
    cudaGetSymbolAddress((void**)&pavh, g_avh);
    cudaGetSymbolAddress((void**)&pavl, g_avl);
    cudaGetSymbolAddress((void**)&pwth, g_wth);
    cudaGetSymbolAddress((void**)&pwtl, g_wtl);
    cudaGetSymbolAddress((void**)&pqh,  g_qh);
    cudaGetSymbolAddress((void**)&pql,  g_ql);
    cudaGetSymbolAddress((void**)&pkh,  g_kh);
    cudaGetSymbolAddress((void**)&pkl,  g_kl);
    cudaGetSymbolAddress((void**)&pvh,  g_vh);
    cudaGetSymbolAddress((void**)&pvl,  g_vl);

    cudaFuncSetAttribute(gemm_mma_kernel, cudaFuncAttributeMaxDynamicSharedMemorySize,
                         GEMM_SMEM);
    cudaFuncSetAttribute(flash_mma_kernel, cudaFuncAttributeMaxDynamicSharedMemorySize,
                         FLASH_SMEM);

    const int XS_GRID = (NTOK*D_/4)/256;
    dim3 wgrid_full(D_/32, D_/128), wgrid_kv(512/32, D_/128), wblk(32, 32);

    // 1) fused time-shift mix + split for k/v paths
    mix_split_kernel<<<XS_GRID, 256>>>(xk, xv, mk, mv, pakh, pakl, pavh, pavl);

    // 2) q-side projections: merged N=4096 GEMM (Wq | Wg)
    split_x_kernel<<<XS_GRID, 256>>>(xq, pah, pal);
    wsplit_t_kernel<<<wgrid_full, wblk>>>(Wq, pwth, pwtl, D_);
    wsplit_t_kernel<<<wgrid_full, wblk>>>(Wg, pwth + (size_t)D_*D_, pwtl + (size_t)D_*D_, D_);
    gemm_mma_kernel<<<dim3(4096/128, NTOK/128), 512, GEMM_SMEM>>>(
        pah, pal, pwth, pwtl, pq, pg, D_);

    // 3) k/v projections
    wsplit_t_kernel<<<wgrid_kv, wblk>>>(Wk, pwth, pwtl, 512);
    gemm_mma_kernel<<<dim3(512/128, NTOK/128), 512, GEMM_SMEM>>>(
        pakh, pakl, pwth, pwtl, pk, nullptr, 512);
    wsplit_t_kernel<<<wgrid_kv, wblk>>>(Wv, pwth, pwtl, 512);
    gemm_mma_kernel<<<dim3(512/128, NTOK/128), 512, GEMM_SMEM>>>(
        pavh, pavl, pwth, pwtl, pv, nullptr, 512);

    // 4) per-head RMS norm (+RoPE for q,k) with bf16 hi/lo split output
    norm_head_split_kernel<<<NTOK*H_,   128>>>(pq, H_,   1, 0.08838834764831845f, pqh, pql);
    norm_head_split_kernel<<<NTOK*KVH_, 128>>>(pk, KVH_, 1, 1.f, pkh, pkl);
    norm_head_split_kernel<<<NTOK*KVH_, 128>>>(pv, KVH_, 0, 1.f, pvh, pvl);

    // 5) causal GQA attention + fused L2-norm/gate/split epilogue
    flash_mma_kernel<<<dim3(T_/128, B_*H_), 256, FLASH_SMEM>>>(
        pqh, pql, pkh, pkl, pvh, pvl, pg, pah, pal);

    // 6) output projection
    wsplit_t_kernel<<<wgrid_full, wblk>>>(Wo, pwth, pwtl, D_);
    gemm_mma_kernel<<<dim3(D_/128, NTOK/128), 512, GEMM_SMEM>>>(
        pah, pal, pwth, pwtl, po, nullptr, D_);

    // 7) final RMS norm + 1/sqrt(2*N_LAYER)
    final_norm_kernel<<<NTOK, 256>>>(po, out);
}

// round 10
// speedup vs baseline: 1.0517x; 1.0517x over previous
#include <cuda_runtime.h>
#include <cuda_bf16.h>
#include <math.h>
#include <stdint.h>

#define B_    2
#define T_    2048
#define D_    2048
#define H_    16
#define KVH_  4
#define HD_   128
#define NTOK  (B_*T_)

// ---------------- scratch (device globals: allocation-free) ----------------
__device__ float g_q  [NTOK*D_];
__device__ float g_k  [NTOK*KVH_*HD_];
__device__ float g_v  [NTOK*KVH_*HD_];
__device__ float g_g  [NTOK*D_];
__device__ float g_o  [NTOK*D_];
// split-bf16 operands
__device__ __align__(16) __nv_bfloat16 g_ah [NTOK*D_];
__device__ __align__(16) __nv_bfloat16 g_al [NTOK*D_];
__device__ __align__(16) __nv_bfloat16 g_akh[NTOK*D_];
__device__ __align__(16) __nv_bfloat16 g_akl[NTOK*D_];
__device__ __align__(16) __nv_bfloat16 g_avh[NTOK*D_];
__device__ __align__(16) __nv_bfloat16 g_avl[NTOK*D_];
__device__ __align__(16) __nv_bfloat16 g_wth[2*D_*D_];
__device__ __align__(16) __nv_bfloat16 g_wtl[2*D_*D_];
// pre-split attention operands
__device__ __align__(16) __nv_bfloat16 g_qh [NTOK*D_];
__device__ __align__(16) __nv_bfloat16 g_ql [NTOK*D_];
__device__ __align__(16) __nv_bfloat16 g_kh [NTOK*KVH_*HD_];
__device__ __align__(16) __nv_bfloat16 g_kl [NTOK*KVH_*HD_];
__device__ __align__(16) __nv_bfloat16 g_vh [NTOK*KVH_*HD_];
__device__ __align__(16) __nv_bfloat16 g_vl [NTOK*KVH_*HD_];

// ================= baseline-ISA helpers =================
__device__ __forceinline__ uint32_t smem_u32(const void* p) {
    uint32_t a;
    asm("{ .reg .u64 t; cvta.to.shared.u64 t, %1; cvt.u32.u64 %0, t; }" : "=r"(a) : "l"(p));
    return a;
}
__device__ __forceinline__ uint32_t sw128(uint32_t off) { return off ^ ((off >> 3) & 0x70); }
__device__ __forceinline__ uint32_t sw256(uint32_t off) { return off ^ ((off >> 4) & 0x70); }

__device__ __forceinline__ void cp_async16(uint32_t dst, const void* src) {
    asm volatile("cp.async.cg.shared.global [%0], [%1], 16;" :: "r"(dst), "l"(src) : "memory");
}
#define CP_COMMIT() asm volatile("cp.async.commit_group;" ::: "memory")
#define CP_WAIT(n)  asm volatile("cp.async.wait_group %0;" :: "n"(n) : "memory")

__device__ __forceinline__ void ldsm_x4(uint32_t* r, uint32_t addr) {
    asm volatile("ldmatrix.sync.aligned.m8n8.x4.shared.b16 {%0,%1,%2,%3}, [%4];"
                 : "=r"(r[0]), "=r"(r[1]), "=r"(r[2]), "=r"(r[3]) : "r"(addr));
}
__device__ __forceinline__ void ldsm_x4_t(uint32_t* r, uint32_t addr) {
    asm volatile("ldmatrix.sync.aligned.m8n8.x4.trans.shared.b16 {%0,%1,%2,%3}, [%4];"
                 : "=r"(r[0]), "=r"(r[1]), "=r"(r[2]), "=r"(r[3]) : "r"(addr));
}
__device__ __forceinline__ void mma16816(float* d, const uint32_t* a, const uint32_t* b) {
    asm volatile("mma.sync.aligned.m16n8k16.row.col.f32.bf16.bf16.f32 "
                 "{%0,%1,%2,%3}, {%4,%5,%6,%7}, {%8,%9}, {%0,%1,%2,%3};"
                 : "+f"(d[0]), "+f"(d[1]), "+f"(d[2]), "+f"(d[3])
                 : "r"(a[0]), "r"(a[1]), "r"(a[2]), "r"(a[3]), "r"(b[0]), "r"(b[1]));
}

// fast exp on the FMA pipe
__device__ __forceinline__ float fast_exp(float x) {
    x = fmaxf(x, -80.f);
    const float LOG2E = 1.4426950408889634f;
    float t = x * LOG2E;
    float r = t + 12582912.f;
    float i = r - 12582912.f;
    float f = t - i;
    uint32_t ib = __float_as_uint(r);
    float sc = __uint_as_float((ib + 127u) << 23);
    float p = 1.3333558146e-3f;
    p = fmaf(p, f, 9.6181291076e-3f);
    p = fmaf(p, f, 5.5504108664e-2f);
    p = fmaf(p, f, 2.4022650696e-1f);
    p = fmaf(p, f, 6.9314718056e-1f);
    p = fmaf(p, f, 1.0f);
    return p * sc;
}

__device__ __forceinline__ void split2(float a, float b, uint32_t& hp, uint32_t& lp) {
    __nv_bfloat16 ha = __float2bfloat16(a), hb = __float2bfloat16(b);
    __nv_bfloat16 la = __float2bfloat16(a - __bfloat162float(ha));
    __nv_bfloat16 lb = __float2bfloat16(b - __bfloat162float(hb));
    hp = ((uint32_t)__bfloat16_as_ushort(hb) << 16) | __bfloat16_as_ushort(ha);
    lp = ((uint32_t)__bfloat16_as_ushort(lb) << 16) | __bfloat16_as_ushort(la);
}

// ================= elementwise kernels =================
__global__ void split_x_kernel(const float* __restrict__ x,
                               __nv_bfloat16* __restrict__ hi,
                               __nv_bfloat16* __restrict__ lo)
{
    int i = blockIdx.x * blockDim.x + threadIdx.x;
    float4 v = ((const float4*)x)[i];
    uint32_t h0, l0, h1, l1;
    split2(v.x, v.y, h0, l0);
    split2(v.z, v.w, h1, l1);
    ((uint2*)hi)[i] = make_uint2(h0, h1);
    ((uint2*)lo)[i] = make_uint2(l0, l1);
}

// fused time-shift mix + bf16 hi/lo split for k and v paths
__global__ void mix_split_kernel(const float* __restrict__ xk, const float* __restrict__ xv,
                                 const float* __restrict__ mk, const float* __restrict__ mv,
                                 __nv_bfloat16* __restrict__ kh, __nv_bfloat16* __restrict__ kl,
                                 __nv_bfloat16* __restrict__ vh, __nv_bfloat16* __restrict__ vl)
{
    const int D4 = D_ / 4;
    int idx = blockIdx.x * blockDim.x + threadIdx.x;
    int d4  = idx & (D4 - 1);
    int tok = idx >> 9;
    int t   = tok & (T_ - 1);

    float4 kc = ((const float4*)xk)[idx];
    float4 vc = ((const float4*)xv)[idx];
    float4 m1 = ((const float4*)mk)[d4];
    float4 m2 = ((const float4*)mv)[d4];
    float4 kp = make_float4(0.f,0.f,0.f,0.f);
    float4 vp = make_float4(0.f,0.f,0.f,0.f);
    if (t > 0) {
        kp = ((const float4*)xk)[idx - D4];
        vp = ((const float4*)xv)[idx - D4];
    }
    float4 r1, r2;
    r1.x = kc.x + m1.x*(kp.x-kc.x);  r1.y = kc.y + m1.y*(kp.y-kc.y);
    r1.z = kc.z + m1.z*(kp.z-kc.z);  r1.w = kc.w + m1.w*(kp.w-kc.w);
    r2.x = vc.x + m2.x*(vp.x-vc.x);  r2.y = vc.y + m2.y*(vp.y-vc.y);
    r2.z = vc.z + m2.z*(vp.z-vc.z);  r2.w = vc.w + m2.w*(vp.w-vc.w);

    uint32_t h0, l0, h1, l1;
    split2(r1.x, r1.y, h0, l0);  split2(r1.z, r1.w, h1, l1);
    ((uint2*)kh)[idx] = make_uint2(h0, h1);
    ((uint2*)kl)[idx] = make_uint2(l0, l1);
    split2(r2.x, r2.y, h0, l0);  split2(r2.z, r2.w, h1, l1);
    ((uint2*)vh)[idx] = make_uint2(h0, h1);
    ((uint2*)vl)[idx] = make_uint2(l0, l1);
}

// W[K=2048, N] -> Wt_hi/lo [N, 2048] transposed split; vectorized 8B stores.
__global__ void wsplit_t_kernel(const float* __restrict__ W,
                                __nv_bfloat16* __restrict__ th,
                                __nv_bfloat16* __restrict__ tl, int N)
{
    __shared__ float s[32][132];
    const int k0 = blockIdx.y * 128, n0 = blockIdx.x * 32;
    const int tx = threadIdx.x, ty = threadIdx.y;
    const int tid = ty * 32 + tx;

#pragma unroll
    for (int i = 0; i < 4; i++) {
        int kk = ty + 32*i;
        s[tx][kk] = W[(size_t)(k0 + kk) * N + n0 + tx];
    }
    __syncthreads();

    const int r = tid >> 5, seg = tid & 31;
    float4 v = *(const float4*)(&s[r][seg << 2]);
    uint32_t h0, l0, h1, l1;
    split2(v.x, v.y, h0, l0);
    split2(v.z, v.w, h1, l1);
    size_t o = ((size_t)(n0 + r) * D_ + k0 + (seg << 2)) >> 2;
    ((uint2*)th)[o] = make_uint2(h0, h1);
    ((uint2*)tl)[o] = make_uint2(l0, l1);
}

#define GK  2048
#define NCH (GK/64)

// ================= BIG split-bf16 GEMM: 256x128 block, 64x64 warp tile =====
// 8 warps (4 M x 2 N); per k16: 16 ldsm_x4 feed 96 MMAs (85 B/MMA smem).
#define BG_A     32768                 /* 256 x 128B */
#define BG_B     16384                 /* 128 x 128B */
#define BG_STAGE (2*BG_A + 2*BG_B)     /* 96 KB */
#define BG_SMEM  (2*BG_STAGE + 1024)

__global__ void __launch_bounds__(256, 1) gemm_mma_big(
    const __nv_bfloat16* __restrict__ ah, const __nv_bfloat16* __restrict__ al,
    const __nv_bfloat16* __restrict__ wth, const __nv_bfloat16* __restrict__ wtl,
    float* __restrict__ C0, float* __restrict__ C1, int cstride)
{
    extern __shared__ char sm[];
    const uint32_t smb   = smem_u32(sm);
    const uint32_t tiles = (smb + 1023u) & ~1023u;

    const int tid  = threadIdx.x;
    const int wid  = tid >> 5, lane = tid & 31;
    const int wm   = wid & 3,  wn   = wid >> 2;     // 4 x 2 warps of 64x64
    const int m0   = blockIdx.y << 8;
    const int n0   = blockIdx.x << 7;

    const __nv_bfloat16* pAh = ah  + (size_t)m0 * GK;
    const __nv_bfloat16* pAl = al  + (size_t)m0 * GK;
    const __nv_bfloat16* pBh = wth + (size_t)n0 * GK;
    const __nv_bfloat16* pBl = wtl + (size_t)n0 * GK;

    float acc[4][8][4];
#pragma unroll
    for (int i = 0; i < 4; i++)
#pragma unroll
        for (int j = 0; j < 8; j++)
#pragma unroll
            for (int q = 0; q < 4; q++) acc[i][j][q] = 0.f;

    auto prefetch = [&](int ch) {
        const uint32_t stage = tiles + (uint32_t)(ch & 1) * BG_STAGE;
        const int ke = ch << 6;
#pragma unroll
        for (int j = 0; j < 8; j++) {                 // A: 256 rows x 128B
            int idx = tid + (j << 8);                 // 0..2047
            int r = idx >> 3, c = idx & 7;
            uint32_t off = sw128((r << 7) + (c << 4));
            const size_t go = (size_t)r * GK + ke + (c << 3);
            cp_async16(stage + off,        pAh + go);
            cp_async16(stage + BG_A + off, pAl + go);
        }
#pragma unroll
        for (int j = 0; j < 4; j++) {                 // B: 128 rows x 128B
            int idx = tid + (j << 8);                 // 0..1023
            int r = idx >> 3, c = idx & 7;
            uint32_t off = sw128((r << 7) + (c << 4));
            const size_t go = (size_t)r * GK + ke + (c << 3);
            cp_async16(stage + 2*BG_A + off,        pBh + go);
            cp_async16(stage + 2*BG_A + BG_B + off, pBl + go);
        }
        CP_COMMIT();
    };

    prefetch(0);

    for (int ch = 0; ch < NCH; ch++) {
        if (ch + 1 < NCH) { prefetch(ch + 1); CP_WAIT(1); }
        else              { CP_WAIT(0); }
        __syncthreads();

        const uint32_t stage = tiles + (uint32_t)(ch & 1) * BG_STAGE;
        const uint32_t sAh = stage,          sAl = stage + BG_A;
        const uint32_t sBh = stage + 2*BG_A, sBl = stage + 2*BG_A + BG_B;

#pragma unroll
        for (int ks = 0; ks < 4; ks++) {
            const int kb = ks << 5;

            uint32_t ahf[4][4], alf[4][4];
#pragma unroll
            for (int mt = 0; mt < 4; mt++) {
                int row = wm*64 + mt*16 + (lane & 15);
                uint32_t off = sw128((uint32_t)(row << 7) + kb + ((lane >> 4) << 4));
                ldsm_x4(ahf[mt], sAh + off);
                ldsm_x4(alf[mt], sAl + off);
            }
            const int brow = wn*64 + (lane & 7) + ((lane >> 4) << 3);
            const int bko  = kb + (((lane >> 3) & 1) << 4);
#pragma unroll
            for (int np = 0; np < 4; np++) {
                uint32_t bh[4], bl[4];
                uint32_t off = sw128((uint32_t)((brow + np*16) << 7) + bko);
                ldsm_x4(bh, sBh + off);
                ldsm_x4(bl, sBl + off);
                // pass 1: hi*hi (8 independent)
#pragma unroll
                for (int mt = 0; mt < 4; mt++) {
                    mma16816(acc[mt][2*np],   ahf[mt], bh);
                    mma16816(acc[mt][2*np+1], ahf[mt], bh + 2);
                }
                // pass 2: hi*lo
#pragma unroll
                for (int mt = 0; mt < 4; mt++) {
                    mma16816(acc[mt][2*np],   ahf[mt], bl);
                    mma16816(acc[mt][2*np+1], ahf[mt], bl + 2);
                }
                // pass 3: lo*hi
#pragma unroll
                for (int mt = 0; mt < 4; mt++) {
                    mma16816(acc[mt][2*np],   alf[mt], bh);
                    mma16816(acc[mt][2*np+1], alf[mt], bh + 2);
                }
            }
        }
        __syncthreads();
    }

    float* C = C0;
    int nc = n0;
    if (C1 != nullptr && n0 >= cstride) { C = C1; nc = n0 - cstride; }

    const int er = lane >> 2, ec = (lane & 3) << 1;
#pragma unroll
    for (int mt = 0; mt < 4; mt++) {
        int r0 = m0 + wm*64 + mt*16 + er;
#pragma unroll
        for (int nt = 0; nt < 8; nt++) {
            int c = nc + wn*64 + nt*8 + ec;
            *(float2*)(C + (size_t)r0      * cstride + c) = make_float2(acc[mt][nt][0], acc[mt][nt][1]);
            *(float2*)(C + (size_t)(r0 + 8)* cstride + c) = make_float2(acc[mt][nt][2], acc[mt][nt][3]);
        }
    }
}

// ========== KV GEMM (proven R7): 128x128 block, 8 warps, 32x64 tile ========
#define TILEB     16384
#define STAGEB    (4*TILEB)
#define GEMM_SMEM (3*STAGEB + 1024)

__global__ void __launch_bounds__(256, 1) gemm_mma_kernel(
    const __nv_bfloat16* __restrict__ ah, const __nv_bfloat16* __restrict__ al,
    const __nv_bfloat16* __restrict__ wth, const __nv_bfloat16* __restrict__ wtl,
    float* __restrict__ C0, float* __restrict__ C1, int cstride)
{
    extern __shared__ char sm[];
    const uint32_t smb   = smem_u32(sm);
    const uint32_t tiles = (smb + 1023u) & ~1023u;

    const int tid  = threadIdx.x;
    const int wid  = tid >> 5, lane = tid & 31;
    const int wm   = wid & 3,  wn   = wid >> 2;
    const int m0   = blockIdx.y << 7;
    const int n0   = blockIdx.x << 7;

    const __nv_bfloat16* srcs[4] = { ah  + (size_t)m0 * GK, al  + (size_t)m0 * GK,
                                     wth + (size_t)n0 * GK, wtl + (size_t)n0 * GK };

    float acc[2][8][4];
#pragma unroll
    for (int i = 0; i < 2; i++)
#pragma unroll
        for (int j = 0; j < 8; j++)
#pragma unroll
            for (int q = 0; q < 4; q++) acc[i][j][q] = 0.f;

    auto prefetch = [&](int ch) {
        const uint32_t stage = tiles + (uint32_t)(ch % 3) * STAGEB;
        const int ke = ch << 6;
#pragma unroll
        for (int t = 0; t < 4; t++) {
            const __nv_bfloat16* s = srcs[t];
#pragma unroll
            for (int j = 0; j < 4; j++) {
                int idx = tid + (j << 8);
                int r   = idx >> 3;
                int c   = idx & 7;
                cp_async16(stage + t * TILEB + sw128((r << 7) + (c << 4)),
                           s + (size_t)r * GK + ke + (c << 3));
            }
        }
        CP_COMMIT();
    };

    prefetch(0);
    prefetch(1);

    for (int ch = 0; ch < NCH; ch++) {
        if (ch + 2 < NCH)      { prefetch(ch + 2); CP_WAIT(2); }
        else if (ch + 1 < NCH) { CP_WAIT(1); }
        else                   { CP_WAIT(0); }
        __syncthreads();

        const uint32_t stage = tiles + (uint32_t)(ch % 3) * STAGEB;
        const uint32_t sAh = stage,            sAl = stage + TILEB;
        const uint32_t sBh = stage + 2*TILEB,  sBl = stage + 3*TILEB;

#pragma unroll
        for (int ks = 0; ks < 4; ks++) {
            const int kb = ks << 5;

            uint32_t ahf[2][4], alf[2][4], bhf[4][4], blf[4][4];
#pragma unroll
            for (int mt = 0; mt < 2; mt++) {
                int row = wm*32 + mt*16 + (lane & 15);
                uint32_t off = sw128((uint32_t)(row << 7) + kb + ((lane >> 4) << 4));
                ldsm_x4(ahf[mt], sAh + off);
                ldsm_x4(alf[mt], sAl + off);
            }
            const int brow4 = wn*64 + (lane & 7) + ((lane >> 4) << 3);
            const int bko   = kb + (((lane >> 3) & 1) << 4);
#pragma unroll
            for (int np = 0; np < 4; np++) {
                uint32_t off = sw128((uint32_t)((brow4 + np*16) << 7) + bko);
                ldsm_x4(bhf[np], sBh + off);
                ldsm_x4(blf[np], sBl + off);
            }
#pragma unroll
            for (int mt = 0; mt < 2; mt++)
#pragma unroll
                for (int np = 0; np < 4; np++) {
                    mma16816(acc[mt][2*np],   ahf[mt], bhf[np]);
                    mma16816(acc[mt][2*np+1], ahf[mt], bhf[np] + 2);
                }
#pragma unroll
            for (int mt = 0; mt < 2; mt++)
#pragma unroll
                for (int np = 0; np < 4; np++) {
                    mma16816(acc[mt][2*np],   ahf[mt], blf[np]);
                    mma16816(acc[mt][2*np+1], ahf[mt], blf[np] + 2);
                }
#pragma unroll
            for (int mt = 0; mt < 2; mt++)
#pragma unroll
                for (int np = 0; np < 4; np++) {
                    mma16816(acc[mt][2*np],   alf[mt], bhf[np]);
                    mma16816(acc[mt][2*np+1], alf[mt], bhf[np] + 2);
                }
        }
        __syncthreads();
    }

    float* C = C0;
    int nc = n0;
    if (C1 != nullptr && n0 >= cstride) { C = C1; nc = n0 - cstride; }

    const int er = lane >> 2, ec = (lane & 3) << 1;
#pragma unroll
    for (int mt = 0; mt < 2; mt++) {
        int r0 = m0 + wm*32 + mt*16 + er;
#pragma unroll
        for (int nt = 0; nt < 8; nt++) {
            int c = nc + wn*64 + nt*8 + ec;
            *(float2*)(C + (size_t)r0      * cstride + c) = make_float2(acc[mt][nt][0], acc[mt][nt][1]);
            *(float2*)(C + (size_t)(r0 + 8)* cstride + c) = make_float2(acc[mt][nt][2], acc[mt][nt][3]);
        }
    }
}

// ------- per-head RMS norm (+ optional RoPE), emits bf16 hi/lo split -------
__global__ void norm_head_split_kernel(const float* __restrict__ x, int heads,
                                       int do_rope, float scale,
                                       __nv_bfloat16* __restrict__ oh,
                                       __nv_bfloat16* __restrict__ ol)
{
    __shared__ float sbuf[4];
    __shared__ float svals[128];
    const int head = blockIdx.x % heads;
    const int tok  = blockIdx.x / heads;
    const int t    = tok % T_;
    const size_t base = (size_t)tok*heads*HD_ + head*HD_;
    const float* p = x + base;
    const int d = threadIdx.x;

    float v  = p[d];
    float ss = v*v;
#pragma unroll
    for (int o = 16; o > 0; o >>= 1) ss += __shfl_xor_sync(0xffffffffu, ss, o);
    if ((d & 31) == 0) sbuf[d >> 5] = ss;
    __syncthreads();
    float tot = sbuf[0] + sbuf[1] + sbuf[2] + sbuf[3];
    float r   = rsqrtf(tot * (1.f/HD_) + 1e-8f);
    float vn  = v * r;
    float f;

    if (do_rope) {
        svals[d] = vn;
        __syncthreads();
        int   j  = d & 63;
        float inv_freq = exp2f(-(float)j * (13.287712379549449f / 64.f));
        float ang = (float)t * inv_freq;
        float sn, cs;
        sincosf(ang, &sn, &cs);
        float partner = svals[d ^ 64];
        f = (d < 64) ? (vn*cs - partner*sn) : (vn*cs + partner*sn);
    } else {
        f = vn;
    }
    f *= scale;
    __nv_bfloat16 h = __float2bfloat16(f);
    __nv_bfloat16 l = __float2bfloat16(f - __bfloat162float(h));
    oh[base + d] = h;
    ol[base + d] = l;
}

// ================= flash attention via mma.sync (fused gate epilogue) ======
#define FQH  0
#define FQL  32768
#define FKV  65536
#define FSTG 65536
#define FLASH_SMEM (FKV + 2*FSTG)

__global__ void __launch_bounds__(256, 1) flash_mma_kernel(
    const __nv_bfloat16* __restrict__ qh, const __nv_bfloat16* __restrict__ ql,
    const __nv_bfloat16* __restrict__ kh, const __nv_bfloat16* __restrict__ kl,
    const __nv_bfloat16* __restrict__ vh, const __nv_bfloat16* __restrict__ vl,
    const float* __restrict__ g,
    __nv_bfloat16* __restrict__ oh_out, __nv_bfloat16* __restrict__ ol_out)
{
    extern __shared__ char sm[];
    const uint32_t smb = smem_u32(sm);

    const int tid  = threadIdx.x;
    const int w    = tid >> 5, lane = tid & 31;
    const int qt   = blockIdx.x;
    const int b    = blockIdx.y >> 4;
    const int h    = blockIdx.y & 15;
    const int kvh  = h >> 2;
    const int qs   = qt << 7;

    {
        const __nv_bfloat16* qgh = qh + ((size_t)(b*T_ + qs))*D_ + h*HD_;
        const __nv_bfloat16* qgl = ql + ((size_t)(b*T_ + qs))*D_ + h*HD_;
#pragma unroll
        for (int it = 0; it < 8; it++) {
            int idx = tid + (it << 8);
            int r = idx >> 4, c = idx & 15;
            uint32_t off = sw256((r << 8) + (c << 4));
            cp_async16(smb + FQH + off, qgh + (size_t)r*D_ + (c << 3));
            cp_async16(smb + FQL + off, qgl + (size_t)r*D_ + (c << 3));
        }
        CP_COMMIT();
    }

    const __nv_bfloat16* kh_b = kh + (size_t)(b*T_)*(KVH_*HD_) + kvh*HD_;
    const __nv_bfloat16* kl_b = kl + (size_t)(b*T_)*(KVH_*HD_) + kvh*HD_;
    const __nv_bfloat16* vh_b = vh + (size_t)(b*T_)*(KVH_*HD_) + kvh*HD_;
    const __nv_bfloat16* vl_b = vl + (size_t)(b*T_)*(KVH_*HD_) + kvh*HD_;

    auto prefetch_kv = [&](int kt) {
        const uint32_t sb = smb + FKV + (uint32_t)(kt & 1)*FSTG;
        const size_t rb = (size_t)(kt << 6) * (KVH_*HD_);
        const __nv_bfloat16* ps[4] = { kh_b + rb, kl_b + rb, vh_b + rb, vl_b + rb };
#pragma unroll
        for (int t = 0; t < 4; t++) {
#pragma unroll
            for (int it = 0; it < 4; it++) {
                int idx = tid + (it << 8);
                int r = idx >> 4, c = idx & 15;
                cp_async16(sb + t*16384 + sw256((r << 8) + (c << 4)),
                           ps[t] + (size_t)r*(KVH_*HD_) + (c << 3));
            }
        }
        CP_COMMIT();
    };

    prefetch_kv(0);

    float o[16][4];
#pragma unroll
    for (int nh = 0; nh < 16; nh++)
#pragma unroll
        for (int qq = 0; qq < 4; qq++) o[nh][qq] = 0.f;
    float m0 = -1e30f, m1 = -1e30f, l0 = 0.f, l1 = 0.f;

    const int nkv = 2*qt + 2;
    for (int kt = 0; kt < nkv; kt++) {
        const int ks = kt << 6;
        if (kt + 1 < nkv) { prefetch_kv(kt + 1); CP_WAIT(1); }
        else              { CP_WAIT(0); }
        __syncthreads();

        const uint32_t sb  = smb + FKV + (uint32_t)(kt & 1)*FSTG;
        const uint32_t sKH = sb, sKL = sb + 16384, sVH = sb + 32768, sVL = sb + 49152;

        float s[8][4];
#pragma unroll
        for (int nt = 0; nt < 8; nt++)
#pragma unroll
            for (int qq = 0; qq < 4; qq++) s[nt][qq] = 0.f;

#pragma unroll
        for (int ks8 = 0; ks8 < 8; ks8++) {
            const int kb = ks8 << 5;
            uint32_t aQh[4], aQl[4], bhf[4][4], blf[4][4];
            {
                int row = (w << 4) + (lane & 15);
                uint32_t off = sw256((uint32_t)(row << 8) + kb + ((lane >> 4) << 4));
                ldsm_x4(aQh, smb + FQH + off);
                ldsm_x4(aQl, smb + FQL + off);
            }
            const int brow4 = (lane & 7) + ((lane >> 4) << 3);
            const int bko   = kb + (((lane >> 3) & 1) << 4);
#pragma unroll
            for (int np = 0; np < 4; np++) {
                uint32_t off = sw256((uint32_t)((brow4 + np*16) << 8) + bko);
                ldsm_x4(bhf[np], sKH + off);
                ldsm_x4(blf[np], sKL + off);
            }
#pragma unroll
            for (int np = 0; np < 4; np++) {
                mma16816(s[2*np],   aQh, bhf[np]);
                mma16816(s[2*np+1], aQh, bhf[np] + 2);
            }
#pragma unroll
            for (int np = 0; np < 4; np++) {
                mma16816(s[2*np],   aQh, blf[np]);
                mma16816(s[2*np+1], aQh, blf[np] + 2);
            }
#pragma unroll
            for (int np = 0; np < 4; np++) {
                mma16816(s[2*np],   aQl, bhf[np]);
                mma16816(s[2*np+1], aQl, bhf[np] + 2);
            }
        }

        if (kt >= 2*qt) {
            const int gr0 = qs + (w << 4) + (lane >> 2);
            const int gc0 = ks + ((lane & 3) << 1);
#pragma unroll
            for (int nt = 0; nt < 8; nt++) {
                int c = gc0 + nt*8;
                if (c     > gr0)     s[nt][0] = -1e30f;
                if (c + 1 > gr0)     s[nt][1] = -1e30f;
                if (c     > gr0 + 8) s[nt][2] = -1e30f;
                if (c + 1 > gr0 + 8) s[nt][3] = -1e30f;
            }
        }

        float mx0 = -1e30f, mx1 = -1e30f;
#pragma unroll
        for (int nt = 0; nt < 8; nt++) {
            mx0 = fmaxf(mx0, fmaxf(s[nt][0], s[nt][1]));
            mx1 = fmaxf(mx1, fmaxf(s[nt][2], s[nt][3]));
        }
        mx0 = fmaxf(mx0, __shfl_xor_sync(0xffffffffu, mx0, 1));
        mx0 = fmaxf(mx0, __shfl_xor_sync(0xffffffffu, mx0, 2));
        mx1 = fmaxf(mx1, __shfl_xor_sync(0xffffffffu, mx1, 1));
        mx1 = fmaxf(mx1, __shfl_xor_sync(0xffffffffu, mx1, 2));
        float m0n = fmaxf(m0, mx0), m1n = fmaxf(m1, mx1);
        float sc0 = fast_exp(m0 - m0n), sc1 = fast_exp(m1 - m1n);
        m0 = m0n; m1 = m1n;

        float sum0 = 0.f, sum1 = 0.f;
#pragma unroll
        for (int nt = 0; nt < 8; nt++) {
            s[nt][0] = fast_exp(s[nt][0] - m0n); sum0 += s[nt][0];
            s[nt][1] = fast_exp(s[nt][1] - m0n); sum0 += s[nt][1];
            s[nt][2] = fast_exp(s[nt][2] - m1n); sum1 += s[nt][2];
            s[nt][3] = fast_exp(s[nt][3] - m1n); sum1 += s[nt][3];
        }
        sum0 += __shfl_xor_sync(0xffffffffu, sum0, 1);
        sum0 += __shfl_xor_sync(0xffffffffu, sum0, 2);
        sum1 += __shfl_xor_sync(0xffffffffu, sum1, 1);
        sum1 += __shfl_xor_sync(0xffffffffu, sum1, 2);
        l0 = l0*sc0 + sum0;
        l1 = l1*sc1 + sum1;

#pragma unroll
        for (int nh = 0; nh < 16; nh++) {
            o[nh][0] *= sc0; o[nh][1] *= sc0;
            o[nh][2] *= sc1; o[nh][3] *= sc1;
        }

#pragma unroll
        for (int j = 0; j < 4; j++) {
            uint32_t aPh[4], aPl[4];
            split2(s[2*j][0],   s[2*j][1],   aPh[0], aPl[0]);
            split2(s[2*j][2],   s[2*j][3],   aPh[1], aPl[1]);
            split2(s[2*j+1][0], s[2*j+1][1], aPh[2], aPl[2]);
            split2(s[2*j+1][2], s[2*j+1][3], aPh[3], aPl[3]);
            const uint32_t vrow = (j << 4) + (lane & 15);
            const uint32_t nsel = (lane >> 4);
#pragma unroll
            for (int pp = 0; pp < 4; pp++) {
                uint32_t bh0[4], bl0[4], bh1[4], bl1[4];
                uint32_t off0 = sw256((vrow << 8) + ((4*pp     + nsel) << 4));
                uint32_t off1 = sw256((vrow << 8) + ((4*pp + 2 + nsel) << 4));
                ldsm_x4_t(bh0, sVH + off0);
                ldsm_x4_t(bl0, sVL + off0);
                ldsm_x4_t(bh1, sVH + off1);
                ldsm_x4_t(bl1, sVL + off1);
                mma16816(o[4*pp],   aPh, bh0);
                mma16816(o[4*pp+1], aPh, bh0 + 2);
                mma16816(o[4*pp+2], aPh, bh1);
                mma16816(o[4*pp+3], aPh, bh1 + 2);
                mma16816(o[4*pp],   aPl, bh0);
                mma16816(o[4*pp+1], aPl, bh0 + 2);
                mma16816(o[4*pp+2], aPl, bh1);
                mma16816(o[4*pp+3], aPl, bh1 + 2);
                mma16816(o[4*pp],   aPh, bl0);
                mma16816(o[4*pp+1], aPh, bl0 + 2);
                mma16816(o[4*pp+2], aPh, bl1);
                mma16816(o[4*pp+3], aPh, bl1 + 2);
            }
        }
        __syncthreads();
    }

    const float inv0 = 1.f / l0, inv1 = 1.f / l1;
    float y0[16][2], y1[16][2];
    float ss0 = 0.f, ss1 = 0.f;
#pragma unroll
    for (int nh = 0; nh < 16; nh++) {
        y0[nh][0] = o[nh][0]*inv0;  y0[nh][1] = o[nh][1]*inv0;
        y1[nh][0] = o[nh][2]*inv1;  y1[nh][1] = o[nh][3]*inv1;
        ss0 += y0[nh][0]*y0[nh][0] + y0[nh][1]*y0[nh][1];
        ss1 += y1[nh][0]*y1[nh][0] + y1[nh][1]*y1[nh][1];
    }
    ss0 += __shfl_xor_sync(0xffffffffu, ss0, 1);
    ss0 += __shfl_xor_sync(0xffffffffu, ss0, 2);
    ss1 += __shfl_xor_sync(0xffffffffu, ss1, 1);
    ss1 += __shfl_xor_sync(0xffffffffu, ss1, 2);
    const float s0 = 1.f / fmaxf(sqrtf(ss0), 1e-12f);
    const float s1 = 1.f / fmaxf(sqrtf(ss1), 1e-12f);

    const int r0 = qs + (w << 4) + (lane >> 2);
    const size_t base0 = ((size_t)(b*T_) + r0)*D_ + h*HD_ + ((lane & 3) << 1);
    const size_t base1 = base0 + (size_t)8*D_;
#pragma unroll
    for (int nh = 0; nh < 16; nh++) {
        float2 gv0 = *(const float2*)(g + base0 + nh*8);
        float2 gv1 = *(const float2*)(g + base1 + nh*8);
        uint32_t hp, lp;
        split2(gv0.x*y0[nh][0]*s0, gv0.y*y0[nh][1]*s0, hp, lp);
        *(uint32_t*)(oh_out + base0 + nh*8) = hp;
        *(uint32_t*)(ol_out + base0 + nh*8) = lp;
        split2(gv1.x*y1[nh][0]*s1, gv1.y*y1[nh][1]*s1, hp, lp);
        *(uint32_t*)(oh_out + base1 + nh*8) = hp;
        *(uint32_t*)(ol_out + base1 + nh*8) = lp;
    }
}

// ---------------- final RMS norm over D, scaled by 1/sqrt(48) ----------------
__global__ void final_norm_kernel(const float* __restrict__ in, float* __restrict__ out)
{
    __shared__ float sbuf[8];
    const int tok = blockIdx.x;
    const float* p = in + (size_t)tok*D_;
    const int base = threadIdx.x * 8;

    float4 a = *(const float4*)(p + base);
    float4 b = *(const float4*)(p + base + 4);
    float ss = a.x*a.x + a.y*a.y + a.z*a.z + a.w*a.w
             + b.x*b.x + b.y*b.y + b.z*b.z + b.w*b.w;
#pragma unroll
    for (int o = 16; o > 0; o >>= 1) ss += __shfl_xor_sync(0xffffffffu, ss, o);
    if ((threadIdx.x & 31) == 0) sbuf[threadIdx.x >> 5] = ss;
    __syncthreads();
    float tot = 0.f;
#pragma unroll
    for (int i = 0; i < 8; i++) tot += sbuf[i];
    float r = rsqrtf(tot * (1.f/D_) + 1e-8f) * 0.14433756729740643f;

    float* q = out + (size_t)tok*D_;
    a.x*=r; a.y*=r; a.z*=r; a.w*=r;
    b.x*=r; b.y*=r; b.z*=r; b.w*=r;
    *(float4*)(q + base)     = a;
    *(float4*)(q + base + 4) = b;
}

// ---------------- launcher ----------------
extern "C" void kernel_launch(void* const* d_in, const int* in_sizes, int n_in,
                              void* d_out, int out_size)
{
    (void)in_sizes; (void)n_in; (void)out_size;
    const float* xq = (const float*)d_in[0];
    const float* xk = (const float*)d_in[1];
    const float* xv = (const float*)d_in[2];
    const float* Wq = (const float*)d_in[3];
    const float* Wk = (const float*)d_in[4];
    const float* Wv = (const float*)d_in[5];
    const float* Wg = (const float*)d_in[6];
    const float* Wo = (const float*)d_in[7];
    const float* mk = (const float*)d_in[8];
    const float* mv = (const float*)d_in[9];
    float* out = (float*)d_out;

    float *pq, *pk, *pv, *pg, *po;
    __nv_bfloat16 *pah, *pal, *pakh, *pakl, *pavh, *pavl, *pwth, *pwtl;
    __nv_bfloat16 *pqh, *pql, *pkh, *pkl, *pvh, *pvl;
    cudaGetSymbolAddress((void**)&pq,   g_q);
    cudaGetSymbolAddress((void**)&pk,   g_k);
    cudaGetSymbolAddress((void**)&pv,   g_v);
    cudaGetSymbolAddress((void**)&pg,   g_g);
    cudaGetSymbolAddress((void**)&po,   g_o);
    cudaGetSymbolAddress((void**)&pah,  g_ah);
    cudaGetSymbolAddress((void**)&pal,  g_al);
    cudaGetSymbolAddress((void**)&pakh, g_akh);
    cudaGetSymbolAddress((void**)&pakl, g_akl);
    cudaGetSymbolAddress((void**)&pavh, g_avh);
    cudaGetSymbolAddress((void**)&pavl, g_avl);
    cudaGetSymbolAddress((void**)&pwth, g_wth);
    cudaGetSymbolAddress((void**)&pwtl, g_wtl);
    cudaGetSymbolAddress((void**)&pqh,  g_qh);
    cudaGetSymbolAddress((void**)&pql,  g_ql);
    cudaGetSymbolAddress((void**)&pkh,  g_kh);
    cudaGetSymbolAddress((void**)&pkl,  g_kl);
    cudaGetSymbolAddress((void**)&pvh,  g_vh);
    cudaGetSymbolAddress((void**)&pvl,  g_vl);

    cudaFuncSetAttribute(gemm_mma_big, cudaFuncAttributeMaxDynamicSharedMemorySize,
                         BG_SMEM);
    cudaFuncSetAttribute(gemm_mma_kernel, cudaFuncAttributeMaxDynamicSharedMemorySize,
                         GEMM_SMEM);
    cudaFuncSetAttribute(flash_mma_kernel, cudaFuncAttributeMaxDynamicSharedMemorySize,
                         FLASH_SMEM);

    const int XS_GRID = (NTOK*D_/4)/256;
    dim3 wgrid_full(D_/32, D_/128), wgrid_kv(512/32, D_/128), wblk(32, 32);

    // 1) fused time-shift mix + split for k/v paths
    mix_split_kernel<<<XS_GRID, 256>>>(xk, xv, mk, mv, pakh, pakl, pavh, pavl);

    // 2) q-side projections: merged N=4096 GEMM (Wq | Wg), 256-row blocks
    split_x_kernel<<<XS_GRID, 256>>>(xq, pah, pal);
    wsplit_t_kernel<<<wgrid_full, wblk>>>(Wq, pwth, pwtl, D_);
    wsplit_t_kernel<<<wgrid_full, wblk>>>(Wg, pwth + (size_t)D_*D_, pwtl + (size_t)D_*D_, D_);
    gemm_mma_big<<<dim3(4096/128, NTOK/256), 256, BG_SMEM>>>(
        pah, pal, pwth, pwtl, pq, pg, D_);

    // 3) k/v projections (128-row kernel; better wave fit at N=512)
    wsplit_t_kernel<<<wgrid_kv, wblk>>>(Wk, pwth, pwtl, 512);
    gemm_mma_kernel<<<dim3(512/128, NTOK/128), 256, GEMM_SMEM>>>(
        pakh, pakl, pwth, pwtl, pk, nullptr, 512);
    wsplit_t_kernel<<<wgrid_kv, wblk>>>(Wv, pwth, pwtl, 512);
    gemm_mma_kernel<<<dim3(512/128, NTOK/128), 256, GEMM_SMEM>>>(
        pavh, pavl, pwth, pwtl, pv, nullptr, 512);

    // 4) per-head RMS norm (+RoPE for q,k) with bf16 hi/lo split output
    norm_head_split_kernel<<<NTOK*H_,   128>>>(pq, H_,   1, 0.08838834764831845f, pqh, pql);
    norm_head_split_kernel<<<NTOK*KVH_, 128>>>(pk, KVH_, 1, 1.f, pkh, pkl);
    norm_head_split_kernel<<<NTOK*KVH_, 128>>>(pv, KVH_, 0, 1.f, pvh, pvl);

    // 5) causal GQA attention + fused L2-norm/gate/split epilogue
    flash_mma_kernel<<<dim3(T_/128, B_*H_), 256, FLASH_SMEM>>>(
        pqh, pql, pkh, pkl, pvh, pvl, pg, pah, pal);

    // 6) output projection (256-row blocks)
    wsplit_t_kernel<<<wgrid_full, wblk>>>(Wo, pwth, pwtl, D_);
    gemm_mma_big<<<dim3(D_/128, NTOK/256), 256, BG_SMEM>>>(
        pah, pal, pwth, pwtl, po, nullptr, D_);

    // 7) final RMS norm + 1/sqrt(2*N_LAYER)
    final_norm_kernel<<<NTOK, 256>>>(po, out);
}

// round 11
// speedup vs baseline: 1.0601x; 1.0080x over previous
#include <cuda_runtime.h>
#include <cuda_bf16.h>
#include <math.h>
#include <stdint.h>

#define B_    2
#define T_    2048
#define D_    2048
#define H_    16
#define KVH_  4
#define HD_   128
#define NTOK  (B_*T_)

// ---------------- scratch (device globals: allocation-free) ----------------
__device__ float g_q  [NTOK*D_];
__device__ float g_k  [NTOK*KVH_*HD_];
__device__ float g_v  [NTOK*KVH_*HD_];
__device__ float g_g  [NTOK*D_];
__device__ float g_o  [NTOK*D_];
// split-bf16 operands
__device__ __align__(16) __nv_bfloat16 g_ah [NTOK*D_];
__device__ __align__(16) __nv_bfloat16 g_al [NTOK*D_];
__device__ __align__(16) __nv_bfloat16 g_akh[NTOK*D_];
__device__ __align__(16) __nv_bfloat16 g_akl[NTOK*D_];
__device__ __align__(16) __nv_bfloat16 g_avh[NTOK*D_];
__device__ __align__(16) __nv_bfloat16 g_avl[NTOK*D_];
__device__ __align__(16) __nv_bfloat16 g_wth [2*D_*D_];
__device__ __align__(16) __nv_bfloat16 g_wtl [2*D_*D_];
__device__ __align__(16) __nv_bfloat16 g_wkth[512*D_];
__device__ __align__(16) __nv_bfloat16 g_wktl[512*D_];
__device__ __align__(16) __nv_bfloat16 g_wvth[512*D_];
__device__ __align__(16) __nv_bfloat16 g_wvtl[512*D_];
// pre-split attention operands
__device__ __align__(16) __nv_bfloat16 g_qh [NTOK*D_];
__device__ __align__(16) __nv_bfloat16 g_ql [NTOK*D_];
__device__ __align__(16) __nv_bfloat16 g_kh [NTOK*KVH_*HD_];
__device__ __align__(16) __nv_bfloat16 g_kl [NTOK*KVH_*HD_];
__device__ __align__(16) __nv_bfloat16 g_vh [NTOK*KVH_*HD_];
__device__ __align__(16) __nv_bfloat16 g_vl [NTOK*KVH_*HD_];

// ================= baseline-ISA helpers =================
__device__ __forceinline__ uint32_t smem_u32(const void* p) {
    uint32_t a;
    asm("{ .reg .u64 t; cvta.to.shared.u64 t, %1; cvt.u32.u64 %0, t; }" : "=r"(a) : "l"(p));
    return a;
}
__device__ __forceinline__ uint32_t sw128(uint32_t off) { return off ^ ((off >> 3) & 0x70); }
__device__ __forceinline__ uint32_t sw256(uint32_t off) { return off ^ ((off >> 4) & 0x70); }

__device__ __forceinline__ void cp_async16(uint32_t dst, const void* src) {
    asm volatile("cp.async.cg.shared.global [%0], [%1], 16;" :: "r"(dst), "l"(src) : "memory");
}
#define CP_COMMIT() asm volatile("cp.async.commit_group;" ::: "memory")
#define CP_WAIT(n)  asm volatile("cp.async.wait_group %0;" :: "n"(n) : "memory")

__device__ __forceinline__ void ldsm_x4(uint32_t* r, uint32_t addr) {
    asm volatile("ldmatrix.sync.aligned.m8n8.x4.shared.b16 {%0,%1,%2,%3}, [%4];"
                 : "=r"(r[0]), "=r"(r[1]), "=r"(r[2]), "=r"(r[3]) : "r"(addr));
}
__device__ __forceinline__ void ldsm_x4_t(uint32_t* r, uint32_t addr) {
    asm volatile("ldmatrix.sync.aligned.m8n8.x4.trans.shared.b16 {%0,%1,%2,%3}, [%4];"
                 : "=r"(r[0]), "=r"(r[1]), "=r"(r[2]), "=r"(r[3]) : "r"(addr));
}
__device__ __forceinline__ void mma16816(float* d, const uint32_t* a, const uint32_t* b) {
    asm volatile("mma.sync.aligned.m16n8k16.row.col.f32.bf16.bf16.f32 "
                 "{%0,%1,%2,%3}, {%4,%5,%6,%7}, {%8,%9}, {%0,%1,%2,%3};"
                 : "+f"(d[0]), "+f"(d[1]), "+f"(d[2]), "+f"(d[3])
                 : "r"(a[0]), "r"(a[1]), "r"(a[2]), "r"(a[3]), "r"(b[0]), "r"(b[1]));
}

// fast exp on the FMA pipe
__device__ __forceinline__ float fast_exp(float x) {
    x = fmaxf(x, -80.f);
    const float LOG2E = 1.4426950408889634f;
    float t = x * LOG2E;
    float r = t + 12582912.f;
    float i = r - 12582912.f;
    float f = t - i;
    uint32_t ib = __float_as_uint(r);
    float sc = __uint_as_float((ib + 127u) << 23);
    float p = 1.3333558146e-3f;
    p = fmaf(p, f, 9.6181291076e-3f);
    p = fmaf(p, f, 5.5504108664e-2f);
    p = fmaf(p, f, 2.4022650696e-1f);
    p = fmaf(p, f, 6.9314718056e-1f);
    p = fmaf(p, f, 1.0f);
    return p * sc;
}

__device__ __forceinline__ void split2(float a, float b, uint32_t& hp, uint32_t& lp) {
    __nv_bfloat16 ha = __float2bfloat16(a), hb = __float2bfloat16(b);
    __nv_bfloat16 la = __float2bfloat16(a - __bfloat162float(ha));
    __nv_bfloat16 lb = __float2bfloat16(b - __bfloat162float(hb));
    hp = ((uint32_t)__bfloat16_as_ushort(hb) << 16) | __bfloat16_as_ushort(ha);
    lp = ((uint32_t)__bfloat16_as_ushort(lb) << 16) | __bfloat16_as_ushort(la);
}

// ================= elementwise kernels =================
__global__ void split_x_kernel(const float* __restrict__ x,
                               __nv_bfloat16* __restrict__ hi,
                               __nv_bfloat16* __restrict__ lo)
{
    int i = blockIdx.x * blockDim.x + threadIdx.x;
    float4 v = ((const float4*)x)[i];
    uint32_t h0, l0, h1, l1;
    split2(v.x, v.y, h0, l0);
    split2(v.z, v.w, h1, l1);
    ((uint2*)hi)[i] = make_uint2(h0, h1);
    ((uint2*)lo)[i] = make_uint2(l0, l1);
}

// fused time-shift mix + bf16 hi/lo split for k and v paths
__global__ void mix_split_kernel(const float* __restrict__ xk, const float* __restrict__ xv,
                                 const float* __restrict__ mk, const float* __restrict__ mv,
                                 __nv_bfloat16* __restrict__ kh, __nv_bfloat16* __restrict__ kl,
                                 __nv_bfloat16* __restrict__ vh, __nv_bfloat16* __restrict__ vl)
{
    const int D4 = D_ / 4;
    int idx = blockIdx.x * blockDim.x + threadIdx.x;
    int d4  = idx & (D4 - 1);
    int tok = idx >> 9;
    int t   = tok & (T_ - 1);

    float4 kc = ((const float4*)xk)[idx];
    float4 vc = ((const float4*)xv)[idx];
    float4 m1 = ((const float4*)mk)[d4];
    float4 m2 = ((const float4*)mv)[d4];
    float4 kp = make_float4(0.f,0.f,0.f,0.f);
    float4 vp = make_float4(0.f,0.f,0.f,0.f);
    if (t > 0) {
        kp = ((const float4*)xk)[idx - D4];
        vp = ((const float4*)xv)[idx - D4];
    }
    float4 r1, r2;
    r1.x = kc.x + m1.x*(kp.x-kc.x);  r1.y = kc.y + m1.y*(kp.y-kc.y);
    r1.z = kc.z + m1.z*(kp.z-kc.z);  r1.w = kc.w + m1.w*(kp.w-kc.w);
    r2.x = vc.x + m2.x*(vp.x-vc.x);  r2.y = vc.y + m2.y*(vp.y-vc.y);
    r2.z = vc.z + m2.z*(vp.z-vc.z);  r2.w = vc.w + m2.w*(vp.w-vc.w);

    uint32_t h0, l0, h1, l1;
    split2(r1.x, r1.y, h0, l0);  split2(r1.z, r1.w, h1, l1);
    ((uint2*)kh)[idx] = make_uint2(h0, h1);
    ((uint2*)kl)[idx] = make_uint2(l0, l1);
    split2(r2.x, r2.y, h0, l0);  split2(r2.z, r2.w, h1, l1);
    ((uint2*)vh)[idx] = make_uint2(h0, h1);
    ((uint2*)vl)[idx] = make_uint2(l0, l1);
}

// W[K=2048, N] -> Wt_hi/lo [N, 2048] transposed split; vectorized 8B stores.
__global__ void wsplit_t_kernel(const float* __restrict__ W,
                                __nv_bfloat16* __restrict__ th,
                                __nv_bfloat16* __restrict__ tl, int N)
{
    __shared__ float s[32][132];
    const int k0 = blockIdx.y * 128, n0 = blockIdx.x * 32;
    const int tx = threadIdx.x, ty = threadIdx.y;
    const int tid = ty * 32 + tx;

#pragma unroll
    for (int i = 0; i < 4; i++) {
        int kk = ty + 32*i;
        s[tx][kk] = W[(size_t)(k0 + kk) * N + n0 + tx];
    }
    __syncthreads();

    const int r = tid >> 5, seg = tid & 31;
    float4 v = *(const float4*)(&s[r][seg << 2]);
    uint32_t h0, l0, h1, l1;
    split2(v.x, v.y, h0, l0);
    split2(v.z, v.w, h1, l1);
    size_t o = ((size_t)(n0 + r) * D_ + k0 + (seg << 2)) >> 2;
    ((uint2*)th)[o] = make_uint2(h0, h1);
    ((uint2*)tl)[o] = make_uint2(l0, l1);
}

#define GK  2048
#define NCH (GK/64)

// ================= BIG split-bf16 GEMM body (256x128 block, 64x64 warps) ===
#define BG_A     32768
#define BG_B     16384
#define BG_STAGE (2*BG_A + 2*BG_B)
#define BG_SMEM  (2*BG_STAGE + 1024)

__device__ __forceinline__ void gemm_big_body(
    const __nv_bfloat16* __restrict__ ah, const __nv_bfloat16* __restrict__ al,
    const __nv_bfloat16* __restrict__ wth, const __nv_bfloat16* __restrict__ wtl,
    float* __restrict__ C0, float* __restrict__ C1, int cstride,
    int m0, int n0, char* sm)
{
    const uint32_t smb   = smem_u32(sm);
    const uint32_t tiles = (smb + 1023u) & ~1023u;

    const int tid  = threadIdx.x;
    const int wid  = tid >> 5, lane = tid & 31;
    const int wm   = wid & 3,  wn   = wid >> 2;

    const __nv_bfloat16* pAh = ah  + (size_t)m0 * GK;
    const __nv_bfloat16* pAl = al  + (size_t)m0 * GK;
    const __nv_bfloat16* pBh = wth + (size_t)n0 * GK;
    const __nv_bfloat16* pBl = wtl + (size_t)n0 * GK;

    float acc[4][8][4];
#pragma unroll
    for (int i = 0; i < 4; i++)
#pragma unroll
        for (int j = 0; j < 8; j++)
#pragma unroll
            for (int q = 0; q < 4; q++) acc[i][j][q] = 0.f;

    auto prefetch = [&](int ch) {
        const uint32_t stage = tiles + (uint32_t)(ch & 1) * BG_STAGE;
        const int ke = ch << 6;
#pragma unroll
        for (int j = 0; j < 8; j++) {
            int idx = tid + (j << 8);
            int r = idx >> 3, c = idx & 7;
            uint32_t off = sw128((r << 7) + (c << 4));
            const size_t go = (size_t)r * GK + ke + (c << 3);
            cp_async16(stage + off,        pAh + go);
            cp_async16(stage + BG_A + off, pAl + go);
        }
#pragma unroll
        for (int j = 0; j < 4; j++) {
            int idx = tid + (j << 8);
            int r = idx >> 3, c = idx & 7;
            uint32_t off = sw128((r << 7) + (c << 4));
            const size_t go = (size_t)r * GK + ke + (c << 3);
            cp_async16(stage + 2*BG_A + off,        pBh + go);
            cp_async16(stage + 2*BG_A + BG_B + off, pBl + go);
        }
        CP_COMMIT();
    };

    prefetch(0);

    for (int ch = 0; ch < NCH; ch++) {
        if (ch + 1 < NCH) { prefetch(ch + 1); CP_WAIT(1); }
        else              { CP_WAIT(0); }
        __syncthreads();

        const uint32_t stage = tiles + (uint32_t)(ch & 1) * BG_STAGE;
        const uint32_t sAh = stage,          sAl = stage + BG_A;
        const uint32_t sBh = stage + 2*BG_A, sBl = stage + 2*BG_A + BG_B;

#pragma unroll
        for (int ks = 0; ks < 4; ks++) {
            const int kb = ks << 5;

            uint32_t ahf[4][4], alf[4][4];
#pragma unroll
            for (int mt = 0; mt < 4; mt++) {
                int row = wm*64 + mt*16 + (lane & 15);
                uint32_t off = sw128((uint32_t)(row << 7) + kb + ((lane >> 4) << 4));
                ldsm_x4(ahf[mt], sAh + off);
                ldsm_x4(alf[mt], sAl + off);
            }
            const int brow = wn*64 + (lane & 7) + ((lane >> 4) << 3);
            const int bko  = kb + (((lane >> 3) & 1) << 4);
#pragma unroll
            for (int np = 0; np < 4; np++) {
                uint32_t bh[4], bl[4];
                uint32_t off = sw128((uint32_t)((brow + np*16) << 7) + bko);
                ldsm_x4(bh, sBh + off);
                ldsm_x4(bl, sBl + off);
#pragma unroll
                for (int mt = 0; mt < 4; mt++) {
                    mma16816(acc[mt][2*np],   ahf[mt], bh);
                    mma16816(acc[mt][2*np+1], ahf[mt], bh + 2);
                }
#pragma unroll
                for (int mt = 0; mt < 4; mt++) {
                    mma16816(acc[mt][2*np],   ahf[mt], bl);
                    mma16816(acc[mt][2*np+1], ahf[mt], bl + 2);
                }
#pragma unroll
                for (int mt = 0; mt < 4; mt++) {
                    mma16816(acc[mt][2*np],   alf[mt], bh);
                    mma16816(acc[mt][2*np+1], alf[mt], bh + 2);
                }
            }
        }
        __syncthreads();
    }

    float* C = C0;
    int nc = n0;
    if (C1 != nullptr && n0 >= cstride) { C = C1; nc = n0 - cstride; }

    const int er = lane >> 2, ec = (lane & 3) << 1;
#pragma unroll
    for (int mt = 0; mt < 4; mt++) {
        int r0 = m0 + wm*64 + mt*16 + er;
#pragma unroll
        for (int nt = 0; nt < 8; nt++) {
            int c = nc + wn*64 + nt*8 + ec;
            *(float2*)(C + (size_t)r0      * cstride + c) = make_float2(acc[mt][nt][0], acc[mt][nt][1]);
            *(float2*)(C + (size_t)(r0 + 8)* cstride + c) = make_float2(acc[mt][nt][2], acc[mt][nt][3]);
        }
    }
}

// standalone big GEMM (Wo projection)
__global__ void __launch_bounds__(256, 1) gemm_mma_big(
    const __nv_bfloat16* __restrict__ ah, const __nv_bfloat16* __restrict__ al,
    const __nv_bfloat16* __restrict__ wth, const __nv_bfloat16* __restrict__ wtl,
    float* __restrict__ C0, float* __restrict__ C1, int cstride)
{
    extern __shared__ char sm[];
    gemm_big_body(ah, al, wth, wtl, C0, C1, cstride,
                  blockIdx.y << 8, blockIdx.x << 7, sm);
}

// fused q/k/v projection GEMM: flat tile index over 3 jobs
// job q: 512 tiles (32 n x 16 m), N=4096 -> pq | pg
// job k: 64 tiles (4 n x 16 m), N=512 -> pk
// job v: 64 tiles
#define QKV_TILES 640
__global__ void __launch_bounds__(256, 1) gemm_mma_qkv(
    const __nv_bfloat16* __restrict__ aqh, const __nv_bfloat16* __restrict__ aql,
    const __nv_bfloat16* __restrict__ akh, const __nv_bfloat16* __restrict__ akl,
    const __nv_bfloat16* __restrict__ avh, const __nv_bfloat16* __restrict__ avl,
    const __nv_bfloat16* __restrict__ wqh, const __nv_bfloat16* __restrict__ wql,
    const __nv_bfloat16* __restrict__ wkh, const __nv_bfloat16* __restrict__ wkl,
    const __nv_bfloat16* __restrict__ wvh, const __nv_bfloat16* __restrict__ wvl,
    float* __restrict__ pq, float* __restrict__ pg,
    float* __restrict__ pk, float* __restrict__ pv)
{
    extern __shared__ char sm[];
    const int idx = blockIdx.x;
    if (idx < 512) {
        gemm_big_body(aqh, aql, wqh, wql, pq, pg, D_,
                      (idx >> 5) << 8, (idx & 31) << 7, sm);
    } else if (idx < 576) {
        const int i = idx - 512;
        gemm_big_body(akh, akl, wkh, wkl, pk, nullptr, 512,
                      (i >> 2) << 8, (i & 3) << 7, sm);
    } else {
        const int i = idx - 576;
        gemm_big_body(avh, avl, wvh, wvl, pv, nullptr, 512,
                      (i >> 2) << 8, (i & 3) << 7, sm);
    }
}

// ------- per-head RMS norm (+ optional RoPE), emits bf16 hi/lo split -------
__global__ void norm_head_split_kernel(const float* __restrict__ x, int heads,
                                       int do_rope, float scale,
                                       __nv_bfloat16* __restrict__ oh,
                                       __nv_bfloat16* __restrict__ ol)
{
    __shared__ float sbuf[4];
    __shared__ float svals[128];
    const int head = blockIdx.x % heads;
    const int tok  = blockIdx.x / heads;
    const int t    = tok % T_;
    const size_t base = (size_t)tok*heads*HD_ + head*HD_;
    const float* p = x + base;
    const int d = threadIdx.x;

    float v  = p[d];
    float ss = v*v;
#pragma unroll
    for (int o = 16; o > 0; o >>= 1) ss += __shfl_xor_sync(0xffffffffu, ss, o);
    if ((d & 31) == 0) sbuf[d >> 5] = ss;
    __syncthreads();
    float tot = sbuf[0] + sbuf[1] + sbuf[2] + sbuf[3];
    float r   = rsqrtf(tot * (1.f/HD_) + 1e-8f);
    float vn  = v * r;
    float f;

    if (do_rope) {
        svals[d] = vn;
        __syncthreads();
        int   j  = d & 63;
        float inv_freq = exp2f(-(float)j * (13.287712379549449f / 64.f));
        float ang = (float)t * inv_freq;
        float sn, cs;
        sincosf(ang, &sn, &cs);
        float partner = svals[d ^ 64];
        f = (d < 64) ? (vn*cs - partner*sn) : (vn*cs + partner*sn);
    } else {
        f = vn;
    }
    f *= scale;
    __nv_bfloat16 h = __float2bfloat16(f);
    __nv_bfloat16 l = __float2bfloat16(f - __bfloat162float(h));
    oh[base + d] = h;
    ol[base + d] = l;
}

// ================= flash attention via mma.sync (fused gate epilogue) ======
#define FQH  0
#define FQL  32768
#define FKV  65536
#define FSTG 65536
#define FLASH_SMEM (FKV + 2*FSTG)

__global__ void __launch_bounds__(256, 1) flash_mma_kernel(
    const __nv_bfloat16* __restrict__ qh, const __nv_bfloat16* __restrict__ ql,
    const __nv_bfloat16* __restrict__ kh, const __nv_bfloat16* __restrict__ kl,
    const __nv_bfloat16* __restrict__ vh, const __nv_bfloat16* __restrict__ vl,
    const float* __restrict__ g,
    __nv_bfloat16* __restrict__ oh_out, __nv_bfloat16* __restrict__ ol_out)
{
    extern __shared__ char sm[];
    const uint32_t smb = smem_u32(sm);

    const int tid  = threadIdx.x;
    const int w    = tid >> 5, lane = tid & 31;
    const int qt   = (gridDim.x - 1) - blockIdx.x;   // LPT: heavy tiles first
    const int b    = blockIdx.y >> 4;
    const int h    = blockIdx.y & 15;
    const int kvh  = h >> 2;
    const int qs   = qt << 7;

    {
        const __nv_bfloat16* qgh = qh + ((size_t)(b*T_ + qs))*D_ + h*HD_;
        const __nv_bfloat16* qgl = ql + ((size_t)(b*T_ + qs))*D_ + h*HD_;
#pragma unroll
        for (int it = 0; it < 8; it++) {
            int idx = tid + (it << 8);
            int r = idx >> 4, c = idx & 15;
            uint32_t off = sw256((r << 8) + (c << 4));
            cp_async16(smb + FQH + off, qgh + (size_t)r*D_ + (c << 3));
            cp_async16(smb + FQL + off, qgl + (size_t)r*D_ + (c << 3));
        }
        CP_COMMIT();
    }

    const __nv_bfloat16* kh_b = kh + (size_t)(b*T_)*(KVH_*HD_) + kvh*HD_;
    const __nv_bfloat16* kl_b = kl + (size_t)(b*T_)*(KVH_*HD_) + kvh*HD_;
    const __nv_bfloat16* vh_b = vh + (size_t)(b*T_)*(KVH_*HD_) + kvh*HD_;
    const __nv_bfloat16* vl_b = vl + (size_t)(b*T_)*(KVH_*HD_) + kvh*HD_;

    auto prefetch_kv = [&](int kt) {
        const uint32_t sb = smb + FKV + (uint32_t)(kt & 1)*FSTG;
        const size_t rb = (size_t)(kt << 6) * (KVH_*HD_);
        const __nv_bfloat16* ps[4] = { kh_b + rb, kl_b + rb, vh_b + rb, vl_b + rb };
#pragma unroll
        for (int t = 0; t < 4; t++) {
#pragma unroll
            for (int it = 0; it < 4; it++) {
                int idx = tid + (it << 8);
                int r = idx >> 4, c = idx & 15;
                cp_async16(sb + t*16384 + sw256((r << 8) + (c << 4)),
                           ps[t] + (size_t)r*(KVH_*HD_) + (c << 3));
            }
        }
        CP_COMMIT();
    };

    prefetch_kv(0);

    float o[16][4];
#pragma unroll
    for (int nh = 0; nh < 16; nh++)
#pragma unroll
        for (int qq = 0; qq < 4; qq++) o[nh][qq] = 0.f;
    float m0 = -1e30f, m1 = -1e30f, l0 = 0.f, l1 = 0.f;

    const int nkv = 2*qt + 2;
    for (int kt = 0; kt < nkv; kt++) {
        const int ks = kt << 6;
        if (kt + 1 < nkv) { prefetch_kv(kt + 1); CP_WAIT(1); }
        else              { CP_WAIT(0); }
        __syncthreads();

        const uint32_t sb  = smb + FKV + (uint32_t)(kt & 1)*FSTG;
        const uint32_t sKH = sb, sKL = sb + 16384, sVH = sb + 32768, sVL = sb + 49152;

        float s[8][4];
#pragma unroll
        for (int nt = 0; nt < 8; nt++)
#pragma unroll
            for (int qq = 0; qq < 4; qq++) s[nt][qq] = 0.f;

#pragma unroll
        for (int ks8 = 0; ks8 < 8; ks8++) {
            const int kb = ks8 << 5;
            uint32_t aQh[4], aQl[4], bhf[4][4], blf[4][4];
            {
                int row = (w << 4) + (lane & 15);
                uint32_t off = sw256((uint32_t)(row << 8) + kb + ((lane >> 4) << 4));
                ldsm_x4(aQh, smb + FQH + off);
                ldsm_x4(aQl, smb + FQL + off);
            }
            const int brow4 = (lane & 7) + ((lane >> 4) << 3);
            const int bko   = kb + (((lane >> 3) & 1) << 4);
#pragma unroll
            for (int np = 0; np < 4; np++) {
                uint32_t off = sw256((uint32_t)((brow4 + np*16) << 8) + bko);
                ldsm_x4(bhf[np], sKH + off);
                ldsm_x4(blf[np], sKL + off);
            }
#pragma unroll
            for (int np = 0; np < 4; np++) {
                mma16816(s[2*np],   aQh, bhf[np]);
                mma16816(s[2*np+1], aQh, bhf[np] + 2);
            }
#pragma unroll
            for (int np = 0; np < 4; np++) {
                mma16816(s[2*np],   aQh, blf[np]);
                mma16816(s[2*np+1], aQh, blf[np] + 2);
            }
#pragma unroll
            for (int np = 0; np < 4; np++) {
                mma16816(s[2*np],   aQl, bhf[np]);
                mma16816(s[2*np+1], aQl, bhf[np] + 2);
            }
        }

        if (kt >= 2*qt) {
            const int gr0 = qs + (w << 4) + (lane >> 2);
            const int gc0 = ks + ((lane & 3) << 1);
#pragma unroll
            for (int nt = 0; nt < 8; nt++) {
                int c = gc0 + nt*8;
                if (c     > gr0)     s[nt][0] = -1e30f;
                if (c + 1 > gr0)     s[nt][1] = -1e30f;
                if (c     > gr0 + 8) s[nt][2] = -1e30f;
                if (c + 1 > gr0 + 8) s[nt][3] = -1e30f;
            }
        }

        float mx0 = -1e30f, mx1 = -1e30f;
#pragma unroll
        for (int nt = 0; nt < 8; nt++) {
            mx0 = fmaxf(mx0, fmaxf(s[nt][0], s[nt][1]));
            mx1 = fmaxf(mx1, fmaxf(s[nt][2], s[nt][3]));
        }
        mx0 = fmaxf(mx0, __shfl_xor_sync(0xffffffffu, mx0, 1));
        mx0 = fmaxf(mx0, __shfl_xor_sync(0xffffffffu, mx0, 2));
        mx1 = fmaxf(mx1, __shfl_xor_sync(0xffffffffu, mx1, 1));
        mx1 = fmaxf(mx1, __shfl_xor_sync(0xffffffffu, mx1, 2));
        float m0n = fmaxf(m0, mx0), m1n = fmaxf(m1, mx1);
        float sc0 = fast_exp(m0 - m0n), sc1 = fast_exp(m1 - m1n);
        m0 = m0n; m1 = m1n;

        float sum0 = 0.f, sum1 = 0.f;
#pragma unroll
        for (int nt = 0; nt < 8; nt++) {
            s[nt][0] = fast_exp(s[nt][0] - m0n); sum0 += s[nt][0];
            s[nt][1] = fast_exp(s[nt][1] - m0n); sum0 += s[nt][1];
            s[nt][2] = fast_exp(s[nt][2] - m1n); sum1 += s[nt][2];
            s[nt][3] = fast_exp(s[nt][3] - m1n); sum1 += s[nt][3];
        }
        sum0 += __shfl_xor_sync(0xffffffffu, sum0, 1);
        sum0 += __shfl_xor_sync(0xffffffffu, sum0, 2);
        sum1 += __shfl_xor_sync(0xffffffffu, sum1, 1);
        sum1 += __shfl_xor_sync(0xffffffffu, sum1, 2);
        l0 = l0*sc0 + sum0;
        l1 = l1*sc1 + sum1;

#pragma unroll
        for (int nh = 0; nh < 16; nh++) {
            o[nh][0] *= sc0; o[nh][1] *= sc0;
            o[nh][2] *= sc1; o[nh][3] *= sc1;
        }

#pragma unroll
        for (int j = 0; j < 4; j++) {
            uint32_t aPh[4], aPl[4];
            split2(s[2*j][0],   s[2*j][1],   aPh[0], aPl[0]);
            split2(s[2*j][2],   s[2*j][3],   aPh[1], aPl[1]);
            split2(s[2*j+1][0], s[2*j+1][1], aPh[2], aPl[2]);
            split2(s[2*j+1][2], s[2*j+1][3], aPh[3], aPl[3]);
            const uint32_t vrow = (j << 4) + (lane & 15);
            const uint32_t nsel = (lane >> 4);
#pragma unroll
            for (int pp = 0; pp < 4; pp++) {
                uint32_t bh0[4], bl0[4], bh1[4], bl1[4];
                uint32_t off0 = sw256((vrow << 8) + ((4*pp     + nsel) << 4));
                uint32_t off1 = sw256((vrow << 8) + ((4*pp + 2 + nsel) << 4));
                ldsm_x4_t(bh0, sVH + off0);
                ldsm_x4_t(bl0, sVL + off0);
                ldsm_x4_t(bh1, sVH + off1);
                ldsm_x4_t(bl1, sVL + off1);
                mma16816(o[4*pp],   aPh, bh0);
                mma16816(o[4*pp+1], aPh, bh0 + 2);
                mma16816(o[4*pp+2], aPh, bh1);
                mma16816(o[4*pp+3], aPh, bh1 + 2);
                mma16816(o[4*pp],   aPl, bh0);
                mma16816(o[4*pp+1], aPl, bh0 + 2);
                mma16816(o[4*pp+2], aPl, bh1);
                mma16816(o[4*pp+3], aPl, bh1 + 2);
                mma16816(o[4*pp],   aPh, bl0);
                mma16816(o[4*pp+1], aPh, bl0 + 2);
                mma16816(o[4*pp+2], aPh, bl1);
                mma16816(o[4*pp+3], aPh, bl1 + 2);
            }
        }
        __syncthreads();
    }

    const float inv0 = 1.f / l0, inv1 = 1.f / l1;
    float y0[16][2], y1[16][2];
    float ss0 = 0.f, ss1 = 0.f;
#pragma unroll
    for (int nh = 0; nh < 16; nh++) {
        y0[nh][0] = o[nh][0]*inv0;  y0[nh][1] = o[nh][1]*inv0;
        y1[nh][0] = o[nh][2]*inv1;  y1[nh][1] = o[nh][3]*inv1;
        ss0 += y0[nh][0]*y0[nh][0] + y0[nh][1]*y0[nh][1];
        ss1 += y1[nh][0]*y1[nh][0] + y1[nh][1]*y1[nh][1];
    }
    ss0 += __shfl_xor_sync(0xffffffffu, ss0, 1);
    ss0 += __shfl_xor_sync(0xffffffffu, ss0, 2);
    ss1 += __shfl_xor_sync(0xffffffffu, ss1, 1);
    ss1 += __shfl_xor_sync(0xffffffffu, ss1, 2);
    const float s0 = 1.f / fmaxf(sqrtf(ss0), 1e-12f);
    const float s1 = 1.f / fmaxf(sqrtf(ss1), 1e-12f);

    const int r0 = qs + (w << 4) + (lane >> 2);
    const size_t base0 = ((size_t)(b*T_) + r0)*D_ + h*HD_ + ((lane & 3) << 1);
    const size_t base1 = base0 + (size_t)8*D_;
#pragma unroll
    for (int nh = 0; nh < 16; nh++) {
        float2 gv0 = *(const float2*)(g + base0 + nh*8);
        float2 gv1 = *(const float2*)(g + base1 + nh*8);
        uint32_t hp, lp;
        split2(gv0.x*y0[nh][0]*s0, gv0.y*y0[nh][1]*s0, hp, lp);
        *(uint32_t*)(oh_out + base0 + nh*8) = hp;
        *(uint32_t*)(ol_out + base0 + nh*8) = lp;
        split2(gv1.x*y1[nh][0]*s1, gv1.y*y1[nh][1]*s1, hp, lp);
        *(uint32_t*)(oh_out + base1 + nh*8) = hp;
        *(uint32_t*)(ol_out + base1 + nh*8) = lp;
    }
}

// ---------------- final RMS norm over D, scaled by 1/sqrt(48) ----------------
__global__ void final_norm_kernel(const float* __restrict__ in, float* __restrict__ out)
{
    __shared__ float sbuf[8];
    const int tok = blockIdx.x;
    const float* p = in + (size_t)tok*D_;
    const int base = threadIdx.x * 8;

    float4 a = *(const float4*)(p + base);
    float4 b = *(const float4*)(p + base + 4);
    float ss = a.x*a.x + a.y*a.y + a.z*a.z + a.w*a.w
             + b.x*b.x + b.y*b.y + b.z*b.z + b.w*b.w;
#pragma unroll
    for (int o = 16; o > 0; o >>= 1) ss += __shfl_xor_sync(0xffffffffu, ss, o);
    if ((threadIdx.x & 31) == 0) sbuf[threadIdx.x >> 5] = ss;
    __syncthreads();
    float tot = 0.f;
#pragma unroll
    for (int i = 0; i < 8; i++) tot += sbuf[i];
    float r = rsqrtf(tot * (1.f/D_) + 1e-8f) * 0.14433756729740643f;

    float* q = out + (size_t)tok*D_;
    a.x*=r; a.y*=r; a.z*=r; a.w*=r;
    b.x*=r; b.y*=r; b.z*=r; b.w*=r;
    *(float4*)(q + base)     = a;
    *(float4*)(q + base + 4) = b;
}

// ---------------- launcher ----------------
extern "C" void kernel_launch(void* const* d_in, const int* in_sizes, int n_in,
                              void* d_out, int out_size)
{
    (void)in_sizes; (void)n_in; (void)out_size;
    const float* xq = (const float*)d_in[0];
    const float* xk = (const float*)d_in[1];
    const float* xv = (const float*)d_in[2];
    const float* Wq = (const float*)d_in[3];
    const float* Wk = (const float*)d_in[4];
    const float* Wv = (const float*)d_in[5];
    const float* Wg = (const float*)d_in[6];
    const float* Wo = (const float*)d_in[7];
    const float* mk = (const float*)d_in[8];
    const float* mv = (const float*)d_in[9];
    float* out = (float*)d_out;

    float *pq, *pk, *pv, *pg, *po;
    __nv_bfloat16 *pah, *pal, *pakh, *pakl, *pavh, *pavl, *pwth, *pwtl;
    __nv_bfloat16 *pwkh, *pwkl, *pwvh, *pwvl;
    __nv_bfloat16 *pqh, *pql, *pkh, *pkl, *pvh, *pvl;
    cudaGetSymbolAddress((void**)&pq,   g_q);
    cudaGetSymbolAddress((void**)&pk,   g_k);
    cudaGetSymbolAddress((void**)&pv,   g_v);
    cudaGetSymbolAddress((void**)&pg,   g_g);
    cudaGetSymbolAddress((void**)&po,   g_o);
    cudaGetSymbolAddress((void**)&pah,  g_ah);
    cudaGetSymbolAddress((void**)&pal,  g_al);
    cudaGetSymbolAddress((void**)&pakh, g_akh);
    cudaGetSymbolAddress((void**)&pakl, g_akl);
    cudaGetSymbolAddress((void**)&pavh, g_avh);
    cudaGetSymbolAddress((void**)&pavl, g_avl);
    cudaGetSymbolAddress((void**)&pwth, g_wth);
    cudaGetSymbolAddress((void**)&pwtl, g_wtl);
    cudaGetSymbolAddress((void**)&pwkh, g_wkth);
    cudaGetSymbolAddress((void**)&pwkl, g_wktl);
    cudaGetSymbolAddress((void**)&pwvh, g_wvth);
    cudaGetSymbolAddress((void**)&pwvl, g_wvtl);
    cudaGetSymbolAddress((void**)&pqh,  g_qh);
    cudaGetSymbolAddress((void**)&pql,  g_ql);
    cudaGetSymbolAddress((void**)&pkh,  g_kh);
    cudaGetSymbolAddress((void**)&pkl,  g_kl);
    cudaGetSymbolAddress((void**)&pvh,  g_vh);
    cudaGetSymbolAddress((void**)&pvl,  g_vl);

    cudaFuncSetAttribute(gemm_mma_big, cudaFuncAttributeMaxDynamicSharedMemorySize,
                         BG_SMEM);
    cudaFuncSetAttribute(gemm_mma_qkv, cudaFuncAttributeMaxDynamicSharedMemorySize,
                         BG_SMEM);
    cudaFuncSetAttribute(flash_mma_kernel, cudaFuncAttributeMaxDynamicSharedMemorySize,
                         FLASH_SMEM);

    const int XS_GRID = (NTOK*D_/4)/256;
    dim3 wgrid_full(D_/32, D_/128), wgrid_kv(512/32, D_/128), wblk(32, 32);

    // 1) fused time-shift mix + split; xq split; weight transposes
    mix_split_kernel<<<XS_GRID, 256>>>(xk, xv, mk, mv, pakh, pakl, pavh, pavl);
    split_x_kernel<<<XS_GRID, 256>>>(xq, pah, pal);
    wsplit_t_kernel<<<wgrid_full, wblk>>>(Wq, pwth, pwtl, D_);
    wsplit_t_kernel<<<wgrid_full, wblk>>>(Wg, pwth + (size_t)D_*D_, pwtl + (size_t)D_*D_, D_);
    wsplit_t_kernel<<<wgrid_kv, wblk>>>(Wk, pwkh, pwkl, 512);
    wsplit_t_kernel<<<wgrid_kv, wblk>>>(Wv, pwvh, pwvl, 512);

    // 2) fused q/k/v/g projections: single 640-tile launch
    gemm_mma_qkv<<<QKV_TILES, 256, BG_SMEM>>>(
        pah, pal, pakh, pakl, pavh, pavl,
        pwth, pwtl, pwkh, pwkl, pwvh, pwvl,
        pq, pg, pk, pv);

    // 3) per-head RMS norm (+RoPE for q,k) with bf16 hi/lo split output
    norm_head_split_kernel<<<NTOK*H_,   128>>>(pq, H_,   1, 0.08838834764831845f, pqh, pql);
    norm_head_split_kernel<<<NTOK*KVH_, 128>>>(pk, KVH_, 1, 1.f, pkh, pkl);
    norm_head_split_kernel<<<NTOK*KVH_, 128>>>(pv, KVH_, 0, 1.f, pvh, pvl);

    // 4) causal GQA attention + fused L2-norm/gate/split epilogue (LPT order)
    flash_mma_kernel<<<dim3(T_/128, B_*H_), 256, FLASH_SMEM>>>(
        pqh, pql, pkh, pkl, pvh, pvl, pg, pah, pal);

    // 5) output projection
    wsplit_t_kernel<<<wgrid_full, wblk>>>(Wo, pwth, pwtl, D_);
    gemm_mma_big<<<dim3(D_/128, NTOK/256), 256, BG_SMEM>>>(
        pah, pal, pwth, pwtl, po, nullptr, D_);

    // 6) final RMS norm + 1/sqrt(2*N_LAYER)
    final_norm_kernel<<<NTOK, 256>>>(po, out);
}